// round 12
// baseline (speedup 1.0000x reference)
#include <cuda_runtime.h>

using ull = unsigned long long;

namespace {
constexpr int CH = 16;
constexpr int H = 192, W = 192;
constexpr unsigned FULL = 0xffffffffu;
constexpr int NT = 256;

// main tile: 28 out rows x 24 out cols; corr rows 0..29; noise rows 34, cols 36
constexpr int NH = 34, NW = 36;
constexpr int SN_FLOATS = CH * NH * NW;      // 19584
// boundary-row h exchange: sB (rows 4w+3) + sT (rows 4w), 9 dj x 8 warps x 24 cols
constexpr int SBUF_FLOATS = 2 * 9 * 8 * 24;  // 3456 per (sB+sT) buffer
constexpr int SMEM_BYTES = (SN_FLOATS + 2 * SBUF_FLOATS) * 4;  // 105984

// top strip: rows 0..3, x-tiles of 96
constexpr int T_NH = 10, T_NW = 108, T_HSR = 96, T_CR = 6;
constexpr int T_SN = CH * T_NH * T_NW;
// side strips: one 24-row band, left+right 4-col strips
constexpr int S_NH = 30, S_NW = 16, S_HSR = 4, S_CR = 26;
constexpr int S_SN = CH * S_NH * S_NW;
constexpr int S_HS = 9 * S_CR * S_HSR;

constexpr int N_MAIN = 448;
constexpr int N_TOP  = 16;
constexpr int N_SIDE = 64;
constexpr int NBLOCKS = N_MAIN + N_TOP + N_SIDE;
}

template<int N> struct Ic { static constexpr int value = N; };

__device__ __forceinline__ ull pk(float lo, float hi) {
    ull r; asm("mov.b64 %0, {%1,%2};" : "=l"(r) : "f"(lo), "f"(hi)); return r;
}
__device__ __forceinline__ void upk(ull v, float& lo, float& hi) {
    asm("mov.b64 {%0,%1}, %2;" : "=f"(lo), "=f"(hi) : "l"(v));
}
__device__ __forceinline__ void ffma2(ull& acc, ull m, ull s) {
    asm("fma.rn.f32x2 %0, %1, %2, %0;" : "+l"(acc) : "l"(m), "l"(s));
}

// strip helper: corr (16ch, 4 cols, 9 dj) + horizontal 3-sum
__device__ __forceinline__ void corr_hsum(const float* __restrict__ base, int chStride,
                                          const ull* __restrict__ cE0,
                                          const ull* __restrict__ cE1,
                                          float (&h)[9][4])
{
    ull aE0[5], aE1[5], aM[4];
    float a0s[4], a3s[4];
    #pragma unroll
    for (int i = 0; i < 5; i++) { aE0[i] = 0ull; aE1[i] = 0ull; }
    #pragma unroll
    for (int i = 0; i < 4; i++) { aM[i] = 0ull; a0s[i] = 0.0f; a3s[i] = 0.0f; }

    #pragma unroll
    for (int c = 0; c < CH; c++) {
        const float* row = base + c * chStride;
        float4 A = *(const float4*)(row);
        float4 B = *(const float4*)(row + 4);
        float4 C = *(const float4*)(row + 8);
        ull E0 = pk(A.x, A.y), E1 = pk(A.z, A.w);
        ull E2 = pk(B.x, B.y), E3 = pk(B.z, B.w);
        ull E4 = pk(C.x, C.y), E5 = pk(C.z, C.w);
        ull m0 = cE0[c], m1 = cE1[c];
        float c0, c1, c2, c3;
        upk(m0, c0, c1); upk(m1, c2, c3);
        ull mM = pk(c1, c2);
        ffma2(aE0[0], m0, E0); ffma2(aE1[0], m1, E1);
        ffma2(aE0[1], m0, E1); ffma2(aE1[1], m1, E2);
        ffma2(aE0[2], m0, E2); ffma2(aE1[2], m1, E3);
        ffma2(aE0[3], m0, E3); ffma2(aE1[3], m1, E4);
        ffma2(aE0[4], m0, E4); ffma2(aE1[4], m1, E5);
        ffma2(aM[0], mM, E1); ffma2(aM[1], mM, E2);
        ffma2(aM[2], mM, E3); ffma2(aM[3], mM, E4);
        a0s[0] = fmaf(c0, A.y, a0s[0]);  a3s[0] = fmaf(c3, B.x, a3s[0]);
        a0s[1] = fmaf(c0, A.w, a0s[1]);  a3s[1] = fmaf(c3, B.z, a3s[1]);
        a0s[2] = fmaf(c0, B.y, a0s[2]);  a3s[2] = fmaf(c3, C.x, a3s[2]);
        a0s[3] = fmaf(c0, B.w, a0s[3]);  a3s[3] = fmaf(c3, C.z, a3s[3]);
    }

    #pragma unroll
    for (int dj = 0; dj < 9; dj++) {
        float c0, c1, c2, c3;
        if ((dj & 1) == 0) {
            upk(aE0[dj >> 1], c0, c1); upk(aE1[dj >> 1], c2, c3);
        } else {
            c0 = a0s[dj >> 1]; upk(aM[dj >> 1], c1, c2); c3 = a3s[dj >> 1];
        }
        float c4 = __shfl_down_sync(FULL, c0, 1);
        float c5 = __shfl_down_sync(FULL, c1, 1);
        float t12 = c1 + c2, t34 = c3 + c4;
        h[dj][0] = c0 + t12;
        h[dj][1] = t12 + c3;
        h[dj][2] = c2 + t34;
        h[dj][3] = t34 + c5;
    }
}

__global__ __launch_bounds__(NT, 2)
void noisecorr_kernel(const float* __restrict__ noise, float* __restrict__ out)
{
    extern __shared__ float smem[];
    const int t   = threadIdx.x;
    const int bid = blockIdx.x;
    const float inv = 1.0f / 144.0f;

    if (bid < N_MAIN) {
        // ============ MAIN: di 4..8 direct + mirrors, 1 barrier / iteration ======
        float* sN = smem;                   // [16][34][36], row0 = y0-1, col0 = tx0-5
        const int b   = bid / 56;
        const int rem = bid - b * 56;
        const int ty  = rem >> 3;
        const int tx  = rem & 7;
        const int y0  = (ty < 6) ? ty * 28 : 164;   // band 6 overlaps band 5 (bitwise-id)
        const int tx0 = tx * 24;
        const float* nb = noise + (size_t)b * CH * H * W;

        // vectorized halo load: aligned LDG.128, split STS (smem offset = 4j-3)
        for (int idx = t; idx < CH * NH * 10; idx += NT) {
            int c   = idx / (NH * 10);
            int r2  = idx - c * (NH * 10);
            int nr  = r2 / 10;
            int j   = r2 - nr * 10;
            int gy = y0 - 1 + nr;
            int gx = tx0 - 8 + 4 * j;
            float4 v = make_float4(0.f, 0.f, 0.f, 0.f);
            if ((unsigned)gy < (unsigned)H && (unsigned)gx < (unsigned)W)
                v = *(const float4*)&nb[(c * H + gy) * W + gx];
            float* dst = &sN[(c * NH + nr) * NW];
            if (j == 0) {
                dst[0] = v.w;
            } else if (j == 9) {
                dst[33] = v.x; dst[34] = v.y; dst[35] = v.z;
            } else {
                int L = 4 * j - 3;
                dst[L] = v.x;
                *(float2*)&dst[L + 1] = make_float2(v.y, v.z);
                dst[L + 3] = v.w;
            }
        }
        __syncthreads();

        const int r  = t >> 3;               // 0..31; rows 30,31 clamped
        const int g  = t & 7;
        const int q0 = g * 4;
        const int qc = min(q0, 24);
        const int rc = min(r, 29);
        const int w  = r >> 2;
        const bool vstore = (r >= 1) && (r <= 28) && (g <= 5);
        const bool sBst = (g < 6) && ((r & 3) == 3) && (r <= 27);             // store row 4w+3
        const bool sTst = (g < 6) && ((r & 3) == 0) && (r >= 4) && (r <= 28); // store row 4w
        // BUGFIX vs R11: boundary READS must also be gated by g<6 (q0<=20);
        // g=6,7 lanes would index past the sB/sT row (len 24) and off the smem end.
        const bool topB = (g < 6) && ((r & 3) == 0) && (r >= 4) && (r <= 28); // hm from sB[w-1]
        const bool botB = (g < 6) && ((r & 3) == 3) && (r >= 1) && (r <= 27); // hp from sT[w+1]
        const bool xs = (tx >= 1) && (tx <= 6);

        ull cE0[CH], cE1[CH];
        #pragma unroll
        for (int c = 0; c < CH; c++) {
            float4 v = *(const float4*)&sN[(c * NH + rc) * NW + qc + 4];
            cE0[c] = pk(v.x * inv, v.y * inv);
            cE1[c] = pk(v.z * inv, v.w * inv);
        }

        const int oy = y0 + r - 1;

        auto run_iter = [&](int k, auto ndjc) {
            constexpr int NDJ = decltype(ndjc)::value;   // 5 (k==0) or 9
            constexpr int NE = (NDJ + 1) / 2;
            constexpr int NO = NDJ / 2;
            ull aE0[NE], aE1[NE], aM[NO];
            float a0s[NO], a3s[NO];
            #pragma unroll
            for (int i = 0; i < NE; i++) { aE0[i] = 0ull; aE1[i] = 0ull; }
            #pragma unroll
            for (int i = 0; i < NO; i++) { aM[i] = 0ull; a0s[i] = 0.f; a3s[i] = 0.f; }

            const float* srow = &sN[(rc + k) * NW + qc];
            #pragma unroll
            for (int c = 0; c < CH; c++) {
                float4 A = *(const float4*)(srow);
                float4 B = *(const float4*)(srow + 4);
                float4 Cv;
                ull E[6];
                E[0] = pk(A.x, A.y); E[1] = pk(A.z, A.w);
                E[2] = pk(B.x, B.y); E[3] = pk(B.z, B.w);
                if constexpr (NDJ == 9) {
                    Cv = *(const float4*)(srow + 8);
                    E[4] = pk(Cv.x, Cv.y); E[5] = pk(Cv.z, Cv.w);
                }
                srow += NH * NW;
                ull m0 = cE0[c], m1 = cE1[c];
                float c0, c1, c2, c3;
                upk(m0, c0, c1); upk(m1, c2, c3);
                ull mM = pk(c1, c2);
                #pragma unroll
                for (int e = 0; e < NE; e++) {
                    ffma2(aE0[e], m0, E[e]); ffma2(aE1[e], m1, E[e + 1]);
                }
                #pragma unroll
                for (int o = 0; o < NO; o++) ffma2(aM[o], mM, E[o + 1]);
                a0s[0] = fmaf(c0, A.y, a0s[0]);  a3s[0] = fmaf(c3, B.x, a3s[0]);
                a0s[1] = fmaf(c0, A.w, a0s[1]);  a3s[1] = fmaf(c3, B.z, a3s[1]);
                if constexpr (NDJ == 9) {
                    a0s[2] = fmaf(c0, B.y, a0s[2]);  a3s[2] = fmaf(c3, Cv.x, a3s[2]);
                    a0s[3] = fmaf(c0, B.w, a0s[3]);  a3s[3] = fmaf(c3, Cv.z, a3s[3]);
                }
            }

            float h[NDJ][4];
            #pragma unroll
            for (int dj = 0; dj < NDJ; dj++) {
                float c0, c1, c2, c3;
                if ((dj & 1) == 0) {
                    upk(aE0[dj >> 1], c0, c1); upk(aE1[dj >> 1], c2, c3);
                } else {
                    c0 = a0s[dj >> 1]; upk(aM[dj >> 1], c1, c2); c3 = a3s[dj >> 1];
                }
                float c4 = __shfl_down_sync(FULL, c0, 1);
                float c5 = __shfl_down_sync(FULL, c1, 1);
                float t12 = c1 + c2, t34 = c3 + c4;
                h[dj][0] = c0 + t12;
                h[dj][1] = t12 + c3;
                h[dj][2] = c2 + t34;
                h[dj][3] = t34 + c5;
            }

            // boundary-row h exchange (double-buffered by k parity) -> 1 bar/iter
            float* sB = smem + SN_FLOATS + (k & 1) * SBUF_FLOATS;
            float* sT = sB + 9 * 8 * 24;
            if (sBst) {
                #pragma unroll
                for (int dj = 0; dj < NDJ; dj++)
                    *(float4*)&sB[(dj * 8 + w) * 24 + q0] =
                        make_float4(h[dj][0], h[dj][1], h[dj][2], h[dj][3]);
            } else if (sTst) {
                #pragma unroll
                for (int dj = 0; dj < NDJ; dj++)
                    *(float4*)&sT[(dj * 8 + w) * 24 + q0] =
                        make_float4(h[dj][0], h[dj][1], h[dj][2], h[dj][3]);
            }
            __syncthreads();

            #pragma unroll
            for (int dj = 0; dj < NDJ; dj++) {
                float hm0 = __shfl_up_sync(FULL, h[dj][0], 8);
                float hm1 = __shfl_up_sync(FULL, h[dj][1], 8);
                float hm2 = __shfl_up_sync(FULL, h[dj][2], 8);
                float hm3 = __shfl_up_sync(FULL, h[dj][3], 8);
                float hp0 = __shfl_down_sync(FULL, h[dj][0], 8);
                float hp1 = __shfl_down_sync(FULL, h[dj][1], 8);
                float hp2 = __shfl_down_sync(FULL, h[dj][2], 8);
                float hp3 = __shfl_down_sync(FULL, h[dj][3], 8);
                if (topB) {
                    float4 v = *(const float4*)&sB[(dj * 8 + w - 1) * 24 + q0];
                    hm0 = v.x; hm1 = v.y; hm2 = v.z; hm3 = v.w;
                }
                if (botB) {
                    float4 v = *(const float4*)&sT[(dj * 8 + w + 1) * 24 + q0];
                    hp0 = v.x; hp1 = v.y; hp2 = v.z; hp3 = v.w;
                }
                if (vstore) {
                    float4 o4;
                    o4.x = hm0 + h[dj][0] + hp0;
                    o4.y = hm1 + h[dj][1] + hp1;
                    o4.z = hm2 + h[dj][2] + hp2;
                    o4.w = hm3 + h[dj][3] + hp3;
                    const int p = (k + 4) * 9 + dj;
                    float* ob = out + (((size_t)b * 81 + p) * H + oy) * W + tx0 + q0;
                    *(float4*)ob = o4;

                    if constexpr (NDJ == 9) {
                        // k>=1 mirror: out_{80-p}(y+k, x+dj-4); y in [4,191], x in [4,187]
                        const int ym = oy + k;
                        if ((unsigned)(ym - 4) < 188u) {
                            const int pm = 80 - p;
                            const int xb = tx0 + q0 + (dj - 4);
                            float* om = out + (((size_t)b * 81 + pm) * H + ym) * W;
                            if (xs) {
                                if ((dj & 1) == 0) {
                                    *(float2*)&om[xb]     = make_float2(o4.x, o4.y);
                                    *(float2*)&om[xb + 2] = make_float2(o4.z, o4.w);
                                } else {
                                    om[xb] = o4.x;
                                    *(float2*)&om[xb + 1] = make_float2(o4.y, o4.z);
                                    om[xb + 3] = o4.w;
                                }
                            } else {
                                if ((unsigned)(xb + 0 - 4) < 184u) om[xb + 0] = o4.x;
                                if ((unsigned)(xb + 1 - 4) < 184u) om[xb + 1] = o4.y;
                                if ((unsigned)(xb + 2 - 4) < 184u) om[xb + 2] = o4.z;
                                if ((unsigned)(xb + 3 - 4) < 184u) om[xb + 3] = o4.w;
                            }
                        }
                    } else {
                        // k==0 mirror (dj<4): out_{44-dj}(y, x+dj-4); x in [0,187]
                        if (dj < 4) {
                            const int pm = 44 - dj;
                            const int xb = tx0 + q0 + (dj - 4);
                            float* om = out + (((size_t)b * 81 + pm) * H + oy) * W;
                            if (xs) {
                                if ((dj & 1) == 0) {
                                    *(float2*)&om[xb]     = make_float2(o4.x, o4.y);
                                    *(float2*)&om[xb + 2] = make_float2(o4.z, o4.w);
                                } else {
                                    om[xb] = o4.x;
                                    *(float2*)&om[xb + 1] = make_float2(o4.y, o4.z);
                                    om[xb + 3] = o4.w;
                                }
                            } else {
                                if ((unsigned)(xb + 0) < 188u) om[xb + 0] = o4.x;
                                if ((unsigned)(xb + 1) < 188u) om[xb + 1] = o4.y;
                                if ((unsigned)(xb + 2) < 188u) om[xb + 2] = o4.z;
                                if ((unsigned)(xb + 3) < 188u) om[xb + 3] = o4.w;
                            }
                        }
                    }
                }
            }
        };

        run_iter(0, Ic<5>{});
        #pragma unroll 1
        for (int k = 1; k < 5; k++)
            run_iter(k, Ic<9>{});

    } else if (bid < N_MAIN + N_TOP) {
        // ===== TOP STRIP: planes di 0..3 (rows 0..3, full width) + di=4 right corner
        float* sN  = smem;
        float* sHS = smem + T_SN;
        const int idx0 = bid - N_MAIN;
        const int b    = idx0 >> 1;
        const int tx0  = (idx0 & 1) * 96;
        const float* nb = noise + (size_t)b * CH * H * W;

        for (int idx = t; idx < T_SN; idx += NT) {
            int c   = idx / (T_NH * T_NW);
            int r2  = idx - c * (T_NH * T_NW);
            int nr  = r2 / T_NW;
            int nc  = r2 - nr * T_NW;
            int gy = nr - 5, gx = tx0 - 5 + nc;
            float v = 0.0f;
            if ((unsigned)gy < (unsigned)H && (unsigned)gx < (unsigned)W)
                v = nb[(c * H + gy) * W + gx];
            sN[idx] = v;
        }
        __syncthreads();

        const int r  = t >> 5;          // 0..7; rows 6,7 clamped
        const int g  = t & 31;
        const int q0 = g * 4;
        const int qc = min(q0, 96);
        const int qv = min(q0, 92);
        const int rc = min(r, 5);
        const bool hstore = (r < 6) && (g < 24);
        const bool vstore = (r >= 1) && (r <= 4) && (g <= 23);
        const int  rv = min(max(r, 1), 4);
        const bool corner = (tx0 == 96) && (q0 == 92);   // x 188..191

        ull cE0[CH], cE1[CH];
        #pragma unroll
        for (int c = 0; c < CH; c++) {
            float4 v = *(const float4*)&sN[(c * T_NH + rc + 4) * T_NW + qc + 4];
            cE0[c] = pk(v.x * inv, v.y * inv);
            cE1[c] = pk(v.z * inv, v.w * inv);
        }

        #pragma unroll 1
        for (int di = 0; di < 5; di++) {
            float h[9][4];
            corr_hsum(&sN[(rc + di) * T_NW + qc], T_NH * T_NW, cE0, cE1, h);

            __syncthreads();
            if (hstore) {
                #pragma unroll
                for (int dj = 0; dj < 9; dj++)
                    *(float4*)&sHS[(dj * T_CR + r) * T_HSR + q0] =
                        make_float4(h[dj][0], h[dj][1], h[dj][2], h[dj][3]);
            }
            __syncthreads();

            const int oy = r - 1;
            #pragma unroll
            for (int dj = 0; dj < 9; dj++) {
                float4 hm = *(const float4*)&sHS[(dj * T_CR + rv - 1) * T_HSR + qv];
                float4 hp = *(const float4*)&sHS[(dj * T_CR + rv + 1) * T_HSR + qv];
                bool st = vstore && (di < 4 || (corner && dj >= 5));
                if (st) {
                    float4 o;
                    o.x = hm.x + h[dj][0] + hp.x;
                    o.y = hm.y + h[dj][1] + hp.y;
                    o.z = hm.z + h[dj][2] + hp.z;
                    o.w = hm.w + h[dj][3] + hp.w;
                    const int p = di * 9 + dj;
                    float* ob = out + (((size_t)b * 81 + p) * H + oy) * W + tx0 + q0;
                    *(float4*)ob = o;
                }
            }
        }
    } else {
        // ===== SIDE STRIPS: planes di 0..3 (cols 0..3 & 188..191) + di=4 right dj>=5
        float* sNL  = smem;
        float* sNR  = smem + S_SN;
        float* sHSL = smem + 2 * S_SN;
        float* sHSR = smem + 2 * S_SN + S_HS;
        const int idx0 = bid - N_MAIN - N_TOP;
        const int b = idx0 >> 3;
        const int k = idx0 & 7;
        const int y0 = (k == 7) ? 168 : 4 + 24 * k;  // overlap rows bitwise-identical
        const float* nb = noise + (size_t)b * CH * H * W;

        for (int idx = t; idx < 2 * S_SN; idx += NT) {
            int side = idx / S_SN;
            int w2   = idx - side * S_SN;
            int c    = w2 / (S_NH * S_NW);
            int r2   = w2 - c * (S_NH * S_NW);
            int nr   = r2 >> 4;
            int nc   = r2 & 15;
            int gy = y0 - 5 + nr;
            int gx = (side ? 183 : -5) + nc;
            float v = 0.0f;
            if ((unsigned)gy < (unsigned)H && (unsigned)gx < (unsigned)W)
                v = nb[(c * H + gy) * W + gx];
            smem[side ? (S_SN + w2) : w2] = v;
        }
        __syncthreads();

        const bool active = (t < 128);
        const int r  = t >> 2;
        const int g  = t & 3;
        const int gg = g & 1;
        const int sd = g >> 1;
        const int q0 = gg * 4;
        const int rc = min(r, 25);
        const bool hstore = active && (gg == 0) && (r < 26);
        const bool vstore = active && (gg == 0) && (r >= 1) && (r <= 24);
        const int  rv = min(max(r, 1), 24);
        float* sNs  = sd ? sNR : sNL;
        float* sHSs = sd ? sHSR : sHSL;
        const int ox = sd ? 188 : 0;

        ull cE0[CH], cE1[CH];
        if (active) {
            #pragma unroll
            for (int c = 0; c < CH; c++) {
                float4 v = *(const float4*)&sNs[(c * S_NH + rc + 4) * S_NW + q0 + 4];
                cE0[c] = pk(v.x * inv, v.y * inv);
                cE1[c] = pk(v.z * inv, v.w * inv);
            }
        }

        #pragma unroll 1
        for (int di = 0; di < 5; di++) {
            float h[9][4];
            if (active)
                corr_hsum(&sNs[(rc + di) * S_NW + q0], S_NH * S_NW, cE0, cE1, h);

            __syncthreads();
            if (hstore) {
                #pragma unroll
                for (int dj = 0; dj < 9; dj++)
                    *(float4*)&sHSs[(dj * S_CR + r) * S_HSR] =
                        make_float4(h[dj][0], h[dj][1], h[dj][2], h[dj][3]);
            }
            __syncthreads();

            if (active) {
                const int oy = y0 + r - 1;
                #pragma unroll
                for (int dj = 0; dj < 9; dj++) {
                    float4 hm = *(const float4*)&sHSs[(dj * S_CR + rv - 1) * S_HSR];
                    float4 hp = *(const float4*)&sHSs[(dj * S_CR + rv + 1) * S_HSR];
                    bool st = vstore && (di < 4 || (sd == 1 && dj >= 5));
                    if (st) {
                        float4 o;
                        o.x = hm.x + h[dj][0] + hp.x;
                        o.y = hm.y + h[dj][1] + hp.y;
                        o.z = hm.z + h[dj][2] + hp.z;
                        o.w = hm.w + h[dj][3] + hp.w;
                        const int p = di * 9 + dj;
                        float* ob = out + (((size_t)b * 81 + p) * H + oy) * W + ox;
                        *(float4*)ob = o;
                    }
                }
            }
        }
    }
}

extern "C" void kernel_launch(void* const* d_in, const int* in_sizes, int n_in,
                              void* d_out, int out_size)
{
    const float* noise = (const float*)d_in[0];
    float* out = (float*)d_out;
    (void)in_sizes; (void)n_in; (void)out_size;

    cudaFuncSetAttribute(noisecorr_kernel,
                         cudaFuncAttributeMaxDynamicSharedMemorySize, SMEM_BYTES);

    noisecorr_kernel<<<NBLOCKS, NT, SMEM_BYTES>>>(noise, out);
}

// round 13
// speedup vs baseline: 1.1163x; 1.1163x over previous
#include <cuda_runtime.h>

using ull = unsigned long long;

namespace {
constexpr int CH = 16;
constexpr int H = 192, W = 192;
constexpr unsigned FULL = 0xffffffffu;
constexpr int NT = 256;

// main tile: 24 out rows x 24 out cols; corr rows 0..25; noise rows 30, cols 36
constexpr int NH = 30, NW = 36;
constexpr int CRH = 26;                      // corr rows stored in sHS
constexpr int HSR = 24;
constexpr int SN_FLOATS  = CH * NH * NW;     // 17280
constexpr int SHS_FLOATS = 9 * CRH * HSR;    // 5616 (one buffer)
constexpr int SMEM_BYTES = (SN_FLOATS + 2 * SHS_FLOATS) * 4;  // 114048

// top strip: rows 0..3, x-tiles of 96
constexpr int T_NH = 10, T_NW = 108, T_HSR = 96, T_CR = 6;
constexpr int T_SN = CH * T_NH * T_NW;
// side strips: one 24-row band, left+right 4-col strips
constexpr int S_NH = 30, S_NW = 16, S_HSR = 4, S_CR = 26;
constexpr int S_SN = CH * S_NH * S_NW;
constexpr int S_HS = 9 * S_CR * S_HSR;

constexpr int N_MAIN = 512;                  // 8 y-bands x 8 x-tiles x 8 batch
constexpr int N_TOP  = 16;
constexpr int N_SIDE = 64;
constexpr int NBLOCKS = N_MAIN + N_TOP + N_SIDE;  // 592 = 2 x 296 slots
}

template<int N> struct Ic { static constexpr int value = N; };

__device__ __forceinline__ ull pk(float lo, float hi) {
    ull r; asm("mov.b64 %0, {%1,%2};" : "=l"(r) : "f"(lo), "f"(hi)); return r;
}
__device__ __forceinline__ void upk(ull v, float& lo, float& hi) {
    asm("mov.b64 {%0,%1}, %2;" : "=f"(lo), "=f"(hi) : "l"(v));
}
__device__ __forceinline__ void ffma2(ull& acc, ull m, ull s) {
    asm("fma.rn.f32x2 %0, %1, %2, %0;" : "+l"(acc) : "l"(m), "l"(s));
}

// strip helper: corr (16ch, 4 cols, 9 dj) + horizontal 3-sum
__device__ __forceinline__ void corr_hsum(const float* __restrict__ base, int chStride,
                                          const ull* __restrict__ cE0,
                                          const ull* __restrict__ cE1,
                                          float (&h)[9][4])
{
    ull aE0[5], aE1[5], aM[4];
    float a0s[4], a3s[4];
    #pragma unroll
    for (int i = 0; i < 5; i++) { aE0[i] = 0ull; aE1[i] = 0ull; }
    #pragma unroll
    for (int i = 0; i < 4; i++) { aM[i] = 0ull; a0s[i] = 0.0f; a3s[i] = 0.0f; }

    #pragma unroll
    for (int c = 0; c < CH; c++) {
        const float* row = base + c * chStride;
        float4 A = *(const float4*)(row);
        float4 B = *(const float4*)(row + 4);
        float4 C = *(const float4*)(row + 8);
        ull E0 = pk(A.x, A.y), E1 = pk(A.z, A.w);
        ull E2 = pk(B.x, B.y), E3 = pk(B.z, B.w);
        ull E4 = pk(C.x, C.y), E5 = pk(C.z, C.w);
        ull m0 = cE0[c], m1 = cE1[c];
        float c0, c1, c2, c3;
        upk(m0, c0, c1); upk(m1, c2, c3);
        ull mM = pk(c1, c2);
        ffma2(aE0[0], m0, E0); ffma2(aE1[0], m1, E1);
        ffma2(aE0[1], m0, E1); ffma2(aE1[1], m1, E2);
        ffma2(aE0[2], m0, E2); ffma2(aE1[2], m1, E3);
        ffma2(aE0[3], m0, E3); ffma2(aE1[3], m1, E4);
        ffma2(aE0[4], m0, E4); ffma2(aE1[4], m1, E5);
        ffma2(aM[0], mM, E1); ffma2(aM[1], mM, E2);
        ffma2(aM[2], mM, E3); ffma2(aM[3], mM, E4);
        a0s[0] = fmaf(c0, A.y, a0s[0]);  a3s[0] = fmaf(c3, B.x, a3s[0]);
        a0s[1] = fmaf(c0, A.w, a0s[1]);  a3s[1] = fmaf(c3, B.z, a3s[1]);
        a0s[2] = fmaf(c0, B.y, a0s[2]);  a3s[2] = fmaf(c3, C.x, a3s[2]);
        a0s[3] = fmaf(c0, B.w, a0s[3]);  a3s[3] = fmaf(c3, C.z, a3s[3]);
    }

    #pragma unroll
    for (int dj = 0; dj < 9; dj++) {
        float c0, c1, c2, c3;
        if ((dj & 1) == 0) {
            upk(aE0[dj >> 1], c0, c1); upk(aE1[dj >> 1], c2, c3);
        } else {
            c0 = a0s[dj >> 1]; upk(aM[dj >> 1], c1, c2); c3 = a3s[dj >> 1];
        }
        float c4 = __shfl_down_sync(FULL, c0, 1);
        float c5 = __shfl_down_sync(FULL, c1, 1);
        float t12 = c1 + c2, t34 = c3 + c4;
        h[dj][0] = c0 + t12;
        h[dj][1] = t12 + c3;
        h[dj][2] = c2 + t34;
        h[dj][3] = t34 + c5;
    }
}

__global__ __launch_bounds__(NT, 2)
void noisecorr_kernel(const float* __restrict__ noise, float* __restrict__ out)
{
    extern __shared__ float smem[];
    const int t   = threadIdx.x;
    const int bid = blockIdx.x;
    const float inv = 1.0f / 144.0f;

    if (bid < N_MAIN) {
        // ====== MAIN: di 4..8 direct + mirrors; double-buffered sHS, 1 bar/iter ===
        float* sN = smem;                   // [16][30][36], row0 = y0-1, col0 = tx0-5
        const int b   = bid >> 6;
        const int rem = bid & 63;
        const int ty  = rem >> 3;
        const int tx  = rem & 7;
        const int y0  = ty * 24;            // 8 exact bands, no overlap
        const int tx0 = tx * 24;
        const float* nb = noise + (size_t)b * CH * H * W;

        // vectorized halo load: aligned LDG.128, split STS (smem offset = 4j-3)
        for (int idx = t; idx < CH * NH * 10; idx += NT) {
            int c   = idx / (NH * 10);
            int r2  = idx - c * (NH * 10);
            int nr  = r2 / 10;
            int j   = r2 - nr * 10;
            int gy = y0 - 1 + nr;
            int gx = tx0 - 8 + 4 * j;
            float4 v = make_float4(0.f, 0.f, 0.f, 0.f);
            if ((unsigned)gy < (unsigned)H && (unsigned)gx < (unsigned)W)
                v = *(const float4*)&nb[(c * H + gy) * W + gx];
            float* dst = &sN[(c * NH + nr) * NW];
            if (j == 0) {
                dst[0] = v.w;
            } else if (j == 9) {
                dst[33] = v.x; dst[34] = v.y; dst[35] = v.z;
            } else {
                int L = 4 * j - 3;
                dst[L] = v.x;
                *(float2*)&dst[L + 1] = make_float2(v.y, v.z);
                dst[L + 3] = v.w;
            }
        }
        __syncthreads();

        const int r  = t >> 3;               // 0..31; rows 26..31 clamped (masked lanes)
        const int g  = t & 7;
        const int q0 = g * 4;
        const int qc = min(q0, 24);
        const int qv = min(q0, 20);
        const int rc = min(r, 25);
        const bool hstore = (r < 26) && (g < 6);
        const bool vstore = (r >= 1) && (r <= 24) && (g <= 5);
        const int  rv = min(max(r, 1), 24);
        const bool xs = (tx >= 1) && (tx <= 6);
        const bool ys = (ty != 7);

        ull cE0[CH], cE1[CH];
        #pragma unroll
        for (int c = 0; c < CH; c++) {
            float4 v = *(const float4*)&sN[(c * NH + rc) * NW + qc + 4];
            cE0[c] = pk(v.x * inv, v.y * inv);
            cE1[c] = pk(v.z * inv, v.w * inv);
        }

        const int oy = y0 + r - 1;

        auto run_iter = [&](int k, auto ndjc) {
            constexpr int NDJ = decltype(ndjc)::value;   // 5 (k==0) or 9
            constexpr int NE = (NDJ + 1) / 2;
            constexpr int NO = NDJ / 2;
            ull aE0[NE], aE1[NE], aM[NO];
            float a0s[NO], a3s[NO];
            #pragma unroll
            for (int i = 0; i < NE; i++) { aE0[i] = 0ull; aE1[i] = 0ull; }
            #pragma unroll
            for (int i = 0; i < NO; i++) { aM[i] = 0ull; a0s[i] = 0.f; a3s[i] = 0.f; }

            const float* srow = &sN[(rc + k) * NW + qc];
            #pragma unroll
            for (int c = 0; c < CH; c++) {
                float4 A = *(const float4*)(srow);
                float4 B = *(const float4*)(srow + 4);
                float4 Cv;
                ull E[6];
                E[0] = pk(A.x, A.y); E[1] = pk(A.z, A.w);
                E[2] = pk(B.x, B.y); E[3] = pk(B.z, B.w);
                if constexpr (NDJ == 9) {
                    Cv = *(const float4*)(srow + 8);
                    E[4] = pk(Cv.x, Cv.y); E[5] = pk(Cv.z, Cv.w);
                }
                srow += NH * NW;
                ull m0 = cE0[c], m1 = cE1[c];
                float c0, c1, c2, c3;
                upk(m0, c0, c1); upk(m1, c2, c3);
                ull mM = pk(c1, c2);
                #pragma unroll
                for (int e = 0; e < NE; e++) {
                    ffma2(aE0[e], m0, E[e]); ffma2(aE1[e], m1, E[e + 1]);
                }
                #pragma unroll
                for (int o = 0; o < NO; o++) ffma2(aM[o], mM, E[o + 1]);
                a0s[0] = fmaf(c0, A.y, a0s[0]);  a3s[0] = fmaf(c3, B.x, a3s[0]);
                a0s[1] = fmaf(c0, A.w, a0s[1]);  a3s[1] = fmaf(c3, B.z, a3s[1]);
                if constexpr (NDJ == 9) {
                    a0s[2] = fmaf(c0, B.y, a0s[2]);  a3s[2] = fmaf(c3, Cv.x, a3s[2]);
                    a0s[3] = fmaf(c0, B.w, a0s[3]);  a3s[3] = fmaf(c3, Cv.z, a3s[3]);
                }
            }

            float h[NDJ][4];
            #pragma unroll
            for (int dj = 0; dj < NDJ; dj++) {
                float c0, c1, c2, c3;
                if ((dj & 1) == 0) {
                    upk(aE0[dj >> 1], c0, c1); upk(aE1[dj >> 1], c2, c3);
                } else {
                    c0 = a0s[dj >> 1]; upk(aM[dj >> 1], c1, c2); c3 = a3s[dj >> 1];
                }
                float c4 = __shfl_down_sync(FULL, c0, 1);
                float c5 = __shfl_down_sync(FULL, c1, 1);
                float t12 = c1 + c2, t34 = c3 + c4;
                h[dj][0] = c0 + t12;
                h[dj][1] = t12 + c3;
                h[dj][2] = c2 + t34;
                h[dj][3] = t34 + c5;
            }

            // double-buffered sHS (k parity) -> no WAR barrier needed
            float* sHS = smem + SN_FLOATS + (k & 1) * SHS_FLOATS;
            if (hstore) {
                #pragma unroll
                for (int dj = 0; dj < NDJ; dj++)
                    *(float4*)&sHS[(dj * CRH + r) * HSR + q0] =
                        make_float4(h[dj][0], h[dj][1], h[dj][2], h[dj][3]);
            }
            __syncthreads();   // the ONLY barrier per iteration

            #pragma unroll
            for (int dj = 0; dj < NDJ; dj++) {
                float4 hm = *(const float4*)&sHS[(dj * CRH + rv - 1) * HSR + qv];
                float4 hp = *(const float4*)&sHS[(dj * CRH + rv + 1) * HSR + qv];
                if (vstore) {
                    float4 o4;
                    o4.x = hm.x + h[dj][0] + hp.x;
                    o4.y = hm.y + h[dj][1] + hp.y;
                    o4.z = hm.z + h[dj][2] + hp.z;
                    o4.w = hm.w + h[dj][3] + hp.w;
                    const int p = (k + 4) * 9 + dj;
                    float* ob = out + (((size_t)b * 81 + p) * H + oy) * W + tx0 + q0;
                    *(float4*)ob = o4;

                    if constexpr (NDJ == 9) {
                        // k>=1 mirror: out_{80-p}(y+k, x+dj-4); y in [4,191], x in [4,187]
                        const int ym = oy + k;
                        if (ys || ym < H) {
                            const int pm = 80 - p;
                            const int xb = tx0 + q0 + (dj - 4);
                            float* om = out + (((size_t)b * 81 + pm) * H + ym) * W;
                            if (xs) {
                                if ((dj & 1) == 0) {
                                    *(float2*)&om[xb]     = make_float2(o4.x, o4.y);
                                    *(float2*)&om[xb + 2] = make_float2(o4.z, o4.w);
                                } else {
                                    om[xb] = o4.x;
                                    *(float2*)&om[xb + 1] = make_float2(o4.y, o4.z);
                                    om[xb + 3] = o4.w;
                                }
                            } else {
                                if ((unsigned)(xb + 0 - 4) < 184u) om[xb + 0] = o4.x;
                                if ((unsigned)(xb + 1 - 4) < 184u) om[xb + 1] = o4.y;
                                if ((unsigned)(xb + 2 - 4) < 184u) om[xb + 2] = o4.z;
                                if ((unsigned)(xb + 3 - 4) < 184u) om[xb + 3] = o4.w;
                            }
                        }
                    } else {
                        // k==0 mirror (dj<4): out_{44-dj}(y, x+dj-4); x in [0,187]
                        if (dj < 4) {
                            const int pm = 44 - dj;
                            const int xb = tx0 + q0 + (dj - 4);
                            float* om = out + (((size_t)b * 81 + pm) * H + oy) * W;
                            if (xs) {
                                if ((dj & 1) == 0) {
                                    *(float2*)&om[xb]     = make_float2(o4.x, o4.y);
                                    *(float2*)&om[xb + 2] = make_float2(o4.z, o4.w);
                                } else {
                                    om[xb] = o4.x;
                                    *(float2*)&om[xb + 1] = make_float2(o4.y, o4.z);
                                    om[xb + 3] = o4.w;
                                }
                            } else {
                                if ((unsigned)(xb + 0) < 188u) om[xb + 0] = o4.x;
                                if ((unsigned)(xb + 1) < 188u) om[xb + 1] = o4.y;
                                if ((unsigned)(xb + 2) < 188u) om[xb + 2] = o4.z;
                                if ((unsigned)(xb + 3) < 188u) om[xb + 3] = o4.w;
                            }
                        }
                    }
                }
            }
        };

        run_iter(0, Ic<5>{});
        #pragma unroll 1
        for (int k = 1; k < 5; k++)
            run_iter(k, Ic<9>{});

    } else if (bid < N_MAIN + N_TOP) {
        // ===== TOP STRIP: planes di 0..3 (rows 0..3, full width) + di=4 right corner
        float* sN  = smem;
        float* sHS = smem + T_SN;
        const int idx0 = bid - N_MAIN;
        const int b    = idx0 >> 1;
        const int tx0  = (idx0 & 1) * 96;
        const float* nb = noise + (size_t)b * CH * H * W;

        for (int idx = t; idx < T_SN; idx += NT) {
            int c   = idx / (T_NH * T_NW);
            int r2  = idx - c * (T_NH * T_NW);
            int nr  = r2 / T_NW;
            int nc  = r2 - nr * T_NW;
            int gy = nr - 5, gx = tx0 - 5 + nc;
            float v = 0.0f;
            if ((unsigned)gy < (unsigned)H && (unsigned)gx < (unsigned)W)
                v = nb[(c * H + gy) * W + gx];
            sN[idx] = v;
        }
        __syncthreads();

        const int r  = t >> 5;          // 0..7; rows 6,7 clamped
        const int g  = t & 31;
        const int q0 = g * 4;
        const int qc = min(q0, 96);
        const int qv = min(q0, 92);
        const int rc = min(r, 5);
        const bool hstore = (r < 6) && (g < 24);
        const bool vstore = (r >= 1) && (r <= 4) && (g <= 23);
        const int  rv = min(max(r, 1), 4);
        const bool corner = (tx0 == 96) && (q0 == 92);   // x 188..191

        ull cE0[CH], cE1[CH];
        #pragma unroll
        for (int c = 0; c < CH; c++) {
            float4 v = *(const float4*)&sN[(c * T_NH + rc + 4) * T_NW + qc + 4];
            cE0[c] = pk(v.x * inv, v.y * inv);
            cE1[c] = pk(v.z * inv, v.w * inv);
        }

        #pragma unroll 1
        for (int di = 0; di < 5; di++) {
            float h[9][4];
            corr_hsum(&sN[(rc + di) * T_NW + qc], T_NH * T_NW, cE0, cE1, h);

            __syncthreads();
            if (hstore) {
                #pragma unroll
                for (int dj = 0; dj < 9; dj++)
                    *(float4*)&sHS[(dj * T_CR + r) * T_HSR + q0] =
                        make_float4(h[dj][0], h[dj][1], h[dj][2], h[dj][3]);
            }
            __syncthreads();

            const int oy = r - 1;
            #pragma unroll
            for (int dj = 0; dj < 9; dj++) {
                float4 hm = *(const float4*)&sHS[(dj * T_CR + rv - 1) * T_HSR + qv];
                float4 hp = *(const float4*)&sHS[(dj * T_CR + rv + 1) * T_HSR + qv];
                bool st = vstore && (di < 4 || (corner && dj >= 5));
                if (st) {
                    float4 o;
                    o.x = hm.x + h[dj][0] + hp.x;
                    o.y = hm.y + h[dj][1] + hp.y;
                    o.z = hm.z + h[dj][2] + hp.z;
                    o.w = hm.w + h[dj][3] + hp.w;
                    const int p = di * 9 + dj;
                    float* ob = out + (((size_t)b * 81 + p) * H + oy) * W + tx0 + q0;
                    *(float4*)ob = o;
                }
            }
        }
    } else {
        // ===== SIDE STRIPS: planes di 0..3 (cols 0..3 & 188..191) + di=4 right dj>=5
        float* sNL  = smem;
        float* sNR  = smem + S_SN;
        float* sHSL = smem + 2 * S_SN;
        float* sHSR = smem + 2 * S_SN + S_HS;
        const int idx0 = bid - N_MAIN - N_TOP;
        const int b = idx0 >> 3;
        const int k = idx0 & 7;
        const int y0 = (k == 7) ? 168 : 4 + 24 * k;  // overlap rows bitwise-identical
        const float* nb = noise + (size_t)b * CH * H * W;

        for (int idx = t; idx < 2 * S_SN; idx += NT) {
            int side = idx / S_SN;
            int w2   = idx - side * S_SN;
            int c    = w2 / (S_NH * S_NW);
            int r2   = w2 - c * (S_NH * S_NW);
            int nr   = r2 >> 4;
            int nc   = r2 & 15;
            int gy = y0 - 5 + nr;
            int gx = (side ? 183 : -5) + nc;
            float v = 0.0f;
            if ((unsigned)gy < (unsigned)H && (unsigned)gx < (unsigned)W)
                v = nb[(c * H + gy) * W + gx];
            smem[side ? (S_SN + w2) : w2] = v;
        }
        __syncthreads();

        const bool active = (t < 128);
        const int r  = t >> 2;
        const int g  = t & 3;
        const int gg = g & 1;
        const int sd = g >> 1;
        const int q0 = gg * 4;
        const int rc = min(r, 25);
        const bool hstore = active && (gg == 0) && (r < 26);
        const bool vstore = active && (gg == 0) && (r >= 1) && (r <= 24);
        const int  rv = min(max(r, 1), 24);
        float* sNs  = sd ? sNR : sNL;
        float* sHSs = sd ? sHSR : sHSL;
        const int ox = sd ? 188 : 0;

        ull cE0[CH], cE1[CH];
        if (active) {
            #pragma unroll
            for (int c = 0; c < CH; c++) {
                float4 v = *(const float4*)&sNs[(c * S_NH + rc + 4) * S_NW + q0 + 4];
                cE0[c] = pk(v.x * inv, v.y * inv);
                cE1[c] = pk(v.z * inv, v.w * inv);
            }
        }

        #pragma unroll 1
        for (int di = 0; di < 5; di++) {
            float h[9][4];
            if (active)
                corr_hsum(&sNs[(rc + di) * S_NW + q0], S_NH * S_NW, cE0, cE1, h);

            __syncthreads();
            if (hstore) {
                #pragma unroll
                for (int dj = 0; dj < 9; dj++)
                    *(float4*)&sHSs[(dj * S_CR + r) * S_HSR] =
                        make_float4(h[dj][0], h[dj][1], h[dj][2], h[dj][3]);
            }
            __syncthreads();

            if (active) {
                const int oy = y0 + r - 1;
                #pragma unroll
                for (int dj = 0; dj < 9; dj++) {
                    float4 hm = *(const float4*)&sHSs[(dj * S_CR + rv - 1) * S_HSR];
                    float4 hp = *(const float4*)&sHSs[(dj * S_CR + rv + 1) * S_HSR];
                    bool st = vstore && (di < 4 || (sd == 1 && dj >= 5));
                    if (st) {
                        float4 o;
                        o.x = hm.x + h[dj][0] + hp.x;
                        o.y = hm.y + h[dj][1] + hp.y;
                        o.z = hm.z + h[dj][2] + hp.z;
                        o.w = hm.w + h[dj][3] + hp.w;
                        const int p = di * 9 + dj;
                        float* ob = out + (((size_t)b * 81 + p) * H + oy) * W + ox;
                        *(float4*)ob = o;
                    }
                }
            }
        }
    }
}

extern "C" void kernel_launch(void* const* d_in, const int* in_sizes, int n_in,
                              void* d_out, int out_size)
{
    const float* noise = (const float*)d_in[0];
    float* out = (float*)d_out;
    (void)in_sizes; (void)n_in; (void)out_size;

    cudaFuncSetAttribute(noisecorr_kernel,
                         cudaFuncAttributeMaxDynamicSharedMemorySize, SMEM_BYTES);

    noisecorr_kernel<<<NBLOCKS, NT, SMEM_BYTES>>>(noise, out);
}

// round 14
// speedup vs baseline: 1.1888x; 1.0650x over previous
#include <cuda_runtime.h>

using ull = unsigned long long;

namespace {
constexpr int CH = 16;
constexpr int H = 192, W = 192;
constexpr size_t HWsz = (size_t)H * W;
constexpr unsigned FULL = 0xffffffffu;
constexpr int NT = 256;
constexpr float SCL = 1.0f / 12.0f;   // applied to BOTH operands -> product carries 1/144

// main tile: 24 out rows x 24 out cols; corr rows 0..25; noise rows 30, cols 36
constexpr int NH = 30, NW = 36;
constexpr int CRH = 26;
constexpr int HSR = 24;
constexpr int SN_FLOATS  = CH * NH * NW;     // 17280
constexpr int SHS_FLOATS = 9 * CRH * HSR;    // 5616 (one buffer)
constexpr int SMEM_BYTES = (SN_FLOATS + 2 * SHS_FLOATS) * 4;  // 114048

// top strip: rows 0..3, x-tiles of 96
constexpr int T_NH = 10, T_NW = 108, T_HSR = 96, T_CR = 6;
constexpr int T_SN = CH * T_NH * T_NW;
// side strips: one 24-row band, left+right 4-col strips
constexpr int S_NH = 30, S_NW = 16, S_HSR = 4, S_CR = 26;
constexpr int S_SN = CH * S_NH * S_NW;
constexpr int S_HS = 9 * S_CR * S_HSR;

constexpr int N_MAIN = 512;
constexpr int N_TOP  = 16;
constexpr int N_SIDE = 64;
constexpr int NBLOCKS = N_MAIN + N_TOP + N_SIDE;  // 592
}

template<int N> struct Ic { static constexpr int value = N; };

struct alignas(16) U2 { ull lo, hi; };   // one LDS.128 -> two even-aligned f32x2 operands

__device__ __forceinline__ ull pk(float lo, float hi) {
    ull r; asm("mov.b64 %0, {%1,%2};" : "=l"(r) : "f"(lo), "f"(hi)); return r;
}
__device__ __forceinline__ void upk(ull v, float& lo, float& hi) {
    asm("mov.b64 {%0,%1}, %2;" : "=f"(lo), "=f"(hi) : "l"(v));
}
__device__ __forceinline__ void ffma2(ull& acc, ull m, ull s) {
    asm("fma.rn.f32x2 %0, %1, %2, %0;" : "+l"(acc) : "l"(m), "l"(s));
}

// strip helper: corr (16ch, 4 cols, 9 dj) + horizontal 3-sum. sN pre-scaled by 1/12.
__device__ __forceinline__ void corr_hsum(const float* __restrict__ base, int chStride,
                                          const ull* __restrict__ cE0,
                                          const ull* __restrict__ cE1,
                                          float (&h)[9][4])
{
    ull aE0[5], aE1[5], aM[4];
    float a0s[4], a3s[4];
    #pragma unroll
    for (int i = 0; i < 5; i++) { aE0[i] = 0ull; aE1[i] = 0ull; }
    #pragma unroll
    for (int i = 0; i < 4; i++) { aM[i] = 0ull; a0s[i] = 0.0f; a3s[i] = 0.0f; }

    #pragma unroll
    for (int c = 0; c < CH; c++) {
        const U2* rowu = (const U2*)(base + c * chStride);
        U2 P0 = rowu[0];   // floats 0..3  -> E0=P0.lo, E1=P0.hi
        U2 P1 = rowu[1];   // floats 4..7  -> E2=P1.lo, E3=P1.hi
        U2 P2 = rowu[2];   // floats 8..11 -> E4=P2.lo, E5=P2.hi
        ull m0 = cE0[c], m1 = cE1[c];
        float c0, c1, c2, c3;
        upk(m0, c0, c1); upk(m1, c2, c3);
        ull mM = pk(c1, c2);
        ffma2(aE0[0], m0, P0.lo); ffma2(aE1[0], m1, P0.hi);
        ffma2(aE0[1], m0, P0.hi); ffma2(aE1[1], m1, P1.lo);
        ffma2(aE0[2], m0, P1.lo); ffma2(aE1[2], m1, P1.hi);
        ffma2(aE0[3], m0, P1.hi); ffma2(aE1[3], m1, P2.lo);
        ffma2(aE0[4], m0, P2.lo); ffma2(aE1[4], m1, P2.hi);
        ffma2(aM[0], mM, P0.hi); ffma2(aM[1], mM, P1.lo);
        ffma2(aM[2], mM, P1.hi); ffma2(aM[3], mM, P2.lo);
        float g0, g1, g2, g3, g4, g5, g6, g7, g8, g9, g10, g11;
        upk(P0.lo, g0, g1); upk(P0.hi, g2, g3);
        upk(P1.lo, g4, g5); upk(P1.hi, g6, g7);
        upk(P2.lo, g8, g9); upk(P2.hi, g10, g11);
        a0s[0] = fmaf(c0, g1, a0s[0]);  a3s[0] = fmaf(c3, g4,  a3s[0]);
        a0s[1] = fmaf(c0, g3, a0s[1]);  a3s[1] = fmaf(c3, g6,  a3s[1]);
        a0s[2] = fmaf(c0, g5, a0s[2]);  a3s[2] = fmaf(c3, g8,  a3s[2]);
        a0s[3] = fmaf(c0, g7, a0s[3]);  a3s[3] = fmaf(c3, g10, a3s[3]);
    }

    #pragma unroll
    for (int dj = 0; dj < 9; dj++) {
        float c0, c1, c2, c3;
        if ((dj & 1) == 0) {
            upk(aE0[dj >> 1], c0, c1); upk(aE1[dj >> 1], c2, c3);
        } else {
            c0 = a0s[dj >> 1]; upk(aM[dj >> 1], c1, c2); c3 = a3s[dj >> 1];
        }
        float c4 = __shfl_down_sync(FULL, c0, 1);
        float c5 = __shfl_down_sync(FULL, c1, 1);
        float t12 = c1 + c2, t34 = c3 + c4;
        h[dj][0] = c0 + t12;
        h[dj][1] = t12 + c3;
        h[dj][2] = c2 + t34;
        h[dj][3] = t34 + c5;
    }
}

__global__ __launch_bounds__(NT, 2)
void noisecorr_kernel(const float* __restrict__ noise, float* __restrict__ out)
{
    extern __shared__ float smem[];
    const int t   = threadIdx.x;
    const int bid = blockIdx.x;

    if (bid < N_MAIN) {
        // ====== MAIN: di 4..8 direct + mirrors; double-buffered sHS, 1 bar/iter ===
        float* sN = smem;                   // [16][30][36], pre-scaled by 1/12
        const int b   = bid >> 6;
        const int rem = bid & 63;
        const int ty  = rem >> 3;
        const int tx  = rem & 7;
        const int y0  = ty * 24;
        const int tx0 = tx * 24;
        const float* nb = noise + (size_t)b * CH * H * W;

        // vectorized halo load: aligned LDG.128, pre-scale, split STS
        for (int idx = t; idx < CH * NH * 10; idx += NT) {
            int c   = idx / (NH * 10);
            int r2  = idx - c * (NH * 10);
            int nr  = r2 / 10;
            int j   = r2 - nr * 10;
            int gy = y0 - 1 + nr;
            int gx = tx0 - 8 + 4 * j;
            float4 v = make_float4(0.f, 0.f, 0.f, 0.f);
            if ((unsigned)gy < (unsigned)H && (unsigned)gx < (unsigned)W)
                v = *(const float4*)&nb[(c * H + gy) * W + gx];
            v.x *= SCL; v.y *= SCL; v.z *= SCL; v.w *= SCL;
            float* dst = &sN[(c * NH + nr) * NW];
            if (j == 0) {
                dst[0] = v.w;
            } else if (j == 9) {
                dst[33] = v.x; dst[34] = v.y; dst[35] = v.z;
            } else {
                int L = 4 * j - 3;
                dst[L] = v.x;
                *(float2*)&dst[L + 1] = make_float2(v.y, v.z);
                dst[L + 3] = v.w;
            }
        }
        __syncthreads();

        const int r  = t >> 3;               // 0..31; rows 26..31 masked
        const int g  = t & 7;
        const int q0 = g * 4;
        const int qc = min(q0, 24);
        const int qv = min(q0, 20);
        const int rc = min(r, 25);
        const bool hstore = (r < 26) && (g < 6);
        const bool vstore = (r >= 1) && (r <= 24) && (g <= 5);
        const int  rv = min(max(r, 1), 24);
        const bool xs = (tx >= 1) && (tx <= 6);
        const bool ys = (ty != 7);

        ull cE0[CH], cE1[CH];
        #pragma unroll
        for (int c = 0; c < CH; c++) {
            U2 cv = *(const U2*)&sN[(c * NH + rc) * NW + qc + 4];
            cE0[c] = cv.lo;
            cE1[c] = cv.hi;
        }

        const int oy = y0 + r - 1;
        float* const obase = out + (size_t)b * 81 * HWsz + (size_t)oy * W + tx0 + q0;

        auto run_iter = [&](int k, auto ndjc) {
            constexpr int NDJ = decltype(ndjc)::value;   // 5 (k==0) or 9
            constexpr int NE = (NDJ + 1) / 2;
            constexpr int NO = NDJ / 2;
            ull aE0[NE], aE1[NE], aM[NO];
            float a0s[NO], a3s[NO];
            #pragma unroll
            for (int i = 0; i < NE; i++) { aE0[i] = 0ull; aE1[i] = 0ull; }
            #pragma unroll
            for (int i = 0; i < NO; i++) { aM[i] = 0ull; a0s[i] = 0.f; a3s[i] = 0.f; }

            const float* srow = &sN[(rc + k) * NW + qc];
            #pragma unroll
            for (int c = 0; c < CH; c++) {
                const U2* rowu = (const U2*)srow;
                U2 P0 = rowu[0];
                U2 P1 = rowu[1];
                U2 P2;
                ull E[6];
                E[0] = P0.lo; E[1] = P0.hi; E[2] = P1.lo; E[3] = P1.hi;
                if constexpr (NDJ == 9) {
                    P2 = rowu[2];
                    E[4] = P2.lo; E[5] = P2.hi;
                }
                srow += NH * NW;
                ull m0 = cE0[c], m1 = cE1[c];
                float c0, c1, c2, c3;
                upk(m0, c0, c1); upk(m1, c2, c3);
                ull mM = pk(c1, c2);
                #pragma unroll
                for (int e = 0; e < NE; e++) {
                    ffma2(aE0[e], m0, E[e]); ffma2(aE1[e], m1, E[e + 1]);
                }
                #pragma unroll
                for (int o = 0; o < NO; o++) ffma2(aM[o], mM, E[o + 1]);
                float g0, g1, g2, g3, g4, g5, g6, g7;
                upk(P0.lo, g0, g1); upk(P0.hi, g2, g3);
                upk(P1.lo, g4, g5); upk(P1.hi, g6, g7);
                a0s[0] = fmaf(c0, g1, a0s[0]);  a3s[0] = fmaf(c3, g4, a3s[0]);
                a0s[1] = fmaf(c0, g3, a0s[1]);  a3s[1] = fmaf(c3, g6, a3s[1]);
                if constexpr (NDJ == 9) {
                    float g8, g9, g10, g11;
                    upk(P2.lo, g8, g9); upk(P2.hi, g10, g11);
                    a0s[2] = fmaf(c0, g5, a0s[2]);  a3s[2] = fmaf(c3, g8,  a3s[2]);
                    a0s[3] = fmaf(c0, g7, a0s[3]);  a3s[3] = fmaf(c3, g10, a3s[3]);
                }
            }

            float h[NDJ][4];
            #pragma unroll
            for (int dj = 0; dj < NDJ; dj++) {
                float c0, c1, c2, c3;
                if ((dj & 1) == 0) {
                    upk(aE0[dj >> 1], c0, c1); upk(aE1[dj >> 1], c2, c3);
                } else {
                    c0 = a0s[dj >> 1]; upk(aM[dj >> 1], c1, c2); c3 = a3s[dj >> 1];
                }
                float c4 = __shfl_down_sync(FULL, c0, 1);
                float c5 = __shfl_down_sync(FULL, c1, 1);
                float t12 = c1 + c2, t34 = c3 + c4;
                h[dj][0] = c0 + t12;
                h[dj][1] = t12 + c3;
                h[dj][2] = c2 + t34;
                h[dj][3] = t34 + c5;
            }

            // double-buffered sHS (k parity) -> no WAR barrier needed
            float* sHS = smem + SN_FLOATS + (k & 1) * SHS_FLOATS;
            if (hstore) {
                #pragma unroll
                for (int dj = 0; dj < NDJ; dj++)
                    *(float4*)&sHS[(dj * CRH + r) * HSR + q0] =
                        make_float4(h[dj][0], h[dj][1], h[dj][2], h[dj][3]);
            }
            __syncthreads();   // the ONLY barrier per iteration

            // strength-reduced store bases for this k
            float* const obk = obase + (size_t)(k + 4) * 9 * HWsz;
            float* const omk9 = obase + 80 * HWsz - (size_t)(k + 4) * 9 * HWsz
                                + (ptrdiff_t)k * W - 4;          // k>=1 mirror base
            float* const omk0 = obase + 44 * HWsz - 4;            // k==0 mirror base

            #pragma unroll
            for (int dj = 0; dj < NDJ; dj++) {
                float4 hm = *(const float4*)&sHS[(dj * CRH + rv - 1) * HSR + qv];
                float4 hp = *(const float4*)&sHS[(dj * CRH + rv + 1) * HSR + qv];
                if (vstore) {
                    float4 o4;
                    o4.x = hm.x + h[dj][0] + hp.x;
                    o4.y = hm.y + h[dj][1] + hp.y;
                    o4.z = hm.z + h[dj][2] + hp.z;
                    o4.w = hm.w + h[dj][3] + hp.w;
                    float* ob = obk + (ptrdiff_t)dj * (ptrdiff_t)HWsz;
                    *(float4*)ob = o4;

                    if constexpr (NDJ == 9) {
                        // k>=1 mirror: out_{80-p}(y+k, x+dj-4); y in [4,191], x in [4,187]
                        const int ym = oy + k;
                        if (ys || ym < H) {
                            const int xb = tx0 + q0 + (dj - 4);
                            float* om = omk9 + (ptrdiff_t)dj * (1 - (ptrdiff_t)HWsz);
                            if (xs) {
                                if ((dj & 1) == 0) {
                                    *(float2*)&om[0] = make_float2(o4.x, o4.y);
                                    *(float2*)&om[2] = make_float2(o4.z, o4.w);
                                } else {
                                    om[0] = o4.x;
                                    *(float2*)&om[1] = make_float2(o4.y, o4.z);
                                    om[3] = o4.w;
                                }
                            } else {
                                if ((unsigned)(xb + 0 - 4) < 184u) om[0] = o4.x;
                                if ((unsigned)(xb + 1 - 4) < 184u) om[1] = o4.y;
                                if ((unsigned)(xb + 2 - 4) < 184u) om[2] = o4.z;
                                if ((unsigned)(xb + 3 - 4) < 184u) om[3] = o4.w;
                            }
                        }
                    } else {
                        // k==0 mirror (dj<4): out_{44-dj}(y, x+dj-4); x in [0,187]
                        if (dj < 4) {
                            const int xb = tx0 + q0 + (dj - 4);
                            float* om = omk0 + (ptrdiff_t)dj * (1 - (ptrdiff_t)HWsz);
                            if (xs) {
                                if ((dj & 1) == 0) {
                                    *(float2*)&om[0] = make_float2(o4.x, o4.y);
                                    *(float2*)&om[2] = make_float2(o4.z, o4.w);
                                } else {
                                    om[0] = o4.x;
                                    *(float2*)&om[1] = make_float2(o4.y, o4.z);
                                    om[3] = o4.w;
                                }
                            } else {
                                if ((unsigned)(xb + 0) < 188u) om[0] = o4.x;
                                if ((unsigned)(xb + 1) < 188u) om[1] = o4.y;
                                if ((unsigned)(xb + 2) < 188u) om[2] = o4.z;
                                if ((unsigned)(xb + 3) < 188u) om[3] = o4.w;
                            }
                        }
                    }
                }
            }
        };

        run_iter(0, Ic<5>{});
        #pragma unroll 1
        for (int k = 1; k < 5; k++)
            run_iter(k, Ic<9>{});

    } else if (bid < N_MAIN + N_TOP) {
        // ===== TOP STRIP: planes di 0..3 (rows 0..3, full width) + di=4 right corner
        float* sN  = smem;
        float* sHS = smem + T_SN;
        const int idx0 = bid - N_MAIN;
        const int b    = idx0 >> 1;
        const int tx0  = (idx0 & 1) * 96;
        const float* nb = noise + (size_t)b * CH * H * W;

        for (int idx = t; idx < T_SN; idx += NT) {
            int c   = idx / (T_NH * T_NW);
            int r2  = idx - c * (T_NH * T_NW);
            int nr  = r2 / T_NW;
            int nc  = r2 - nr * T_NW;
            int gy = nr - 5, gx = tx0 - 5 + nc;
            float v = 0.0f;
            if ((unsigned)gy < (unsigned)H && (unsigned)gx < (unsigned)W)
                v = nb[(c * H + gy) * W + gx] * SCL;
            sN[idx] = v;
        }
        __syncthreads();

        const int r  = t >> 5;          // 0..7; rows 6,7 masked
        const int g  = t & 31;
        const int q0 = g * 4;
        const int qc = min(q0, 96);
        const int qv = min(q0, 92);
        const int rc = min(r, 5);
        const bool hstore = (r < 6) && (g < 24);
        const bool vstore = (r >= 1) && (r <= 4) && (g <= 23);
        const int  rv = min(max(r, 1), 4);
        const bool corner = (tx0 == 96) && (q0 == 92);   // x 188..191

        ull cE0[CH], cE1[CH];
        #pragma unroll
        for (int c = 0; c < CH; c++) {
            U2 cv = *(const U2*)&sN[(c * T_NH + rc + 4) * T_NW + qc + 4];
            cE0[c] = cv.lo;
            cE1[c] = cv.hi;
        }

        #pragma unroll 1
        for (int di = 0; di < 5; di++) {
            float h[9][4];
            corr_hsum(&sN[(rc + di) * T_NW + qc], T_NH * T_NW, cE0, cE1, h);

            __syncthreads();
            if (hstore) {
                #pragma unroll
                for (int dj = 0; dj < 9; dj++)
                    *(float4*)&sHS[(dj * T_CR + r) * T_HSR + q0] =
                        make_float4(h[dj][0], h[dj][1], h[dj][2], h[dj][3]);
            }
            __syncthreads();

            const int oy = r - 1;
            #pragma unroll
            for (int dj = 0; dj < 9; dj++) {
                float4 hm = *(const float4*)&sHS[(dj * T_CR + rv - 1) * T_HSR + qv];
                float4 hp = *(const float4*)&sHS[(dj * T_CR + rv + 1) * T_HSR + qv];
                bool st = vstore && (di < 4 || (corner && dj >= 5));
                if (st) {
                    float4 o;
                    o.x = hm.x + h[dj][0] + hp.x;
                    o.y = hm.y + h[dj][1] + hp.y;
                    o.z = hm.z + h[dj][2] + hp.z;
                    o.w = hm.w + h[dj][3] + hp.w;
                    const int p = di * 9 + dj;
                    float* ob = out + (((size_t)b * 81 + p) * H + oy) * W + tx0 + q0;
                    *(float4*)ob = o;
                }
            }
        }
    } else {
        // ===== SIDE STRIPS: planes di 0..3 (cols 0..3 & 188..191) + di=4 right dj>=5
        float* sNL  = smem;
        float* sNR  = smem + S_SN;
        float* sHSL = smem + 2 * S_SN;
        float* sHSR = smem + 2 * S_SN + S_HS;
        const int idx0 = bid - N_MAIN - N_TOP;
        const int b = idx0 >> 3;
        const int k = idx0 & 7;
        const int y0 = (k == 7) ? 168 : 4 + 24 * k;  // overlap rows bitwise-identical
        const float* nb = noise + (size_t)b * CH * H * W;

        for (int idx = t; idx < 2 * S_SN; idx += NT) {
            int side = idx / S_SN;
            int w2   = idx - side * S_SN;
            int c    = w2 / (S_NH * S_NW);
            int r2   = w2 - c * (S_NH * S_NW);
            int nr   = r2 >> 4;
            int nc   = r2 & 15;
            int gy = y0 - 5 + nr;
            int gx = (side ? 183 : -5) + nc;
            float v = 0.0f;
            if ((unsigned)gy < (unsigned)H && (unsigned)gx < (unsigned)W)
                v = nb[(c * H + gy) * W + gx] * SCL;
            smem[side ? (S_SN + w2) : w2] = v;
        }
        __syncthreads();

        const bool active = (t < 128);
        const int r  = t >> 2;
        const int g  = t & 3;
        const int gg = g & 1;
        const int sd = g >> 1;
        const int q0 = gg * 4;
        const int rc = min(r, 25);
        const bool hstore = active && (gg == 0) && (r < 26);
        const bool vstore = active && (gg == 0) && (r >= 1) && (r <= 24);
        const int  rv = min(max(r, 1), 24);
        float* sNs  = sd ? sNR : sNL;
        float* sHSs = sd ? sHSR : sHSL;
        const int ox = sd ? 188 : 0;

        ull cE0[CH], cE1[CH];
        if (active) {
            #pragma unroll
            for (int c = 0; c < CH; c++) {
                U2 cv = *(const U2*)&sNs[(c * S_NH + rc + 4) * S_NW + q0 + 4];
                cE0[c] = cv.lo;
                cE1[c] = cv.hi;
            }
        }

        #pragma unroll 1
        for (int di = 0; di < 5; di++) {
            float h[9][4];
            if (active)
                corr_hsum(&sNs[(rc + di) * S_NW + q0], S_NH * S_NW, cE0, cE1, h);

            __syncthreads();
            if (hstore) {
                #pragma unroll
                for (int dj = 0; dj < 9; dj++)
                    *(float4*)&sHSs[(dj * S_CR + r) * S_HSR] =
                        make_float4(h[dj][0], h[dj][1], h[dj][2], h[dj][3]);
            }
            __syncthreads();

            if (active) {
                const int oy = y0 + r - 1;
                #pragma unroll
                for (int dj = 0; dj < 9; dj++) {
                    float4 hm = *(const float4*)&sHSs[(dj * S_CR + rv - 1) * S_HSR];
                    float4 hp = *(const float4*)&sHSs[(dj * S_CR + rv + 1) * S_HSR];
                    bool st = vstore && (di < 4 || (sd == 1 && dj >= 5));
                    if (st) {
                        float4 o;
                        o.x = hm.x + h[dj][0] + hp.x;
                        o.y = hm.y + h[dj][1] + hp.y;
                        o.z = hm.z + h[dj][2] + hp.z;
                        o.w = hm.w + h[dj][3] + hp.w;
                        const int p = di * 9 + dj;
                        float* ob = out + (((size_t)b * 81 + p) * H + oy) * W + ox;
                        *(float4*)ob = o;
                    }
                }
            }
        }
    }
}

extern "C" void kernel_launch(void* const* d_in, const int* in_sizes, int n_in,
                              void* d_out, int out_size)
{
    const float* noise = (const float*)d_in[0];
    float* out = (float*)d_out;
    (void)in_sizes; (void)n_in; (void)out_size;

    cudaFuncSetAttribute(noisecorr_kernel,
                         cudaFuncAttributeMaxDynamicSharedMemorySize, SMEM_BYTES);

    noisecorr_kernel<<<NBLOCKS, NT, SMEM_BYTES>>>(noise, out);
}

// round 15
// speedup vs baseline: 1.2342x; 1.0382x over previous
#include <cuda_runtime.h>

using ull = unsigned long long;

namespace {
constexpr int CH = 16;
constexpr int H = 192, W = 192;
constexpr size_t HWsz = (size_t)H * W;
constexpr unsigned FULL = 0xffffffffu;
constexpr int NT = 256;
constexpr float SCL = 1.0f / 12.0f;   // both operands scaled -> product carries 1/144

constexpr int NH = 30, NW = 36;
constexpr int CRH = 26;
constexpr int HSR = 24;
constexpr int SN_FLOATS  = CH * NH * NW;     // 17280
constexpr int SHS_FLOATS = 9 * CRH * HSR;    // 5616
constexpr int SMEM_BYTES = (SN_FLOATS + 2 * SHS_FLOATS) * 4;  // 114048

constexpr int T_NH = 10, T_NW = 108, T_HSR = 96, T_CR = 6;
constexpr int T_SN = CH * T_NH * T_NW;
constexpr int S_NH = 30, S_NW = 16, S_HSR = 4, S_CR = 26;
constexpr int S_SN = CH * S_NH * S_NW;
constexpr int S_HS = 9 * S_CR * S_HSR;

constexpr int N_MAIN = 512;
constexpr int N_TOP  = 16;
constexpr int N_SIDE = 64;
constexpr int NBLOCKS = N_MAIN + N_TOP + N_SIDE;  // 592
}

template<int N> struct Ic { static constexpr int value = N; };

struct alignas(16) U2 { ull lo, hi; };

__device__ __forceinline__ ull pk(float lo, float hi) {
    ull r; asm("mov.b64 %0, {%1,%2};" : "=l"(r) : "f"(lo), "f"(hi)); return r;
}
__device__ __forceinline__ void upk(ull v, float& lo, float& hi) {
    asm("mov.b64 {%0,%1}, %2;" : "=f"(lo), "=f"(hi) : "l"(v));
}
__device__ __forceinline__ void ffma2(ull& acc, ull m, ull s) {
    asm("fma.rn.f32x2 %0, %1, %2, %0;" : "+l"(acc) : "l"(m), "l"(s));
}
__device__ __forceinline__ ull add2(ull a, ull b) {
    ull r; asm("add.rn.f32x2 %0, %1, %2;" : "=l"(r) : "l"(a), "l"(b)); return r;
}

// strip helper: corr (16ch, 4 cols, 9 dj) + horizontal 3-sum. sN pre-scaled.
__device__ __forceinline__ void corr_hsum(const float* __restrict__ base, int chStride,
                                          const ull* __restrict__ cE0,
                                          const ull* __restrict__ cE1,
                                          float (&h)[9][4])
{
    ull aE0[5], aE1[5], aM[4];
    float a0s[4], a3s[4];
    #pragma unroll
    for (int i = 0; i < 5; i++) { aE0[i] = 0ull; aE1[i] = 0ull; }
    #pragma unroll
    for (int i = 0; i < 4; i++) { aM[i] = 0ull; a0s[i] = 0.0f; a3s[i] = 0.0f; }

    #pragma unroll
    for (int c = 0; c < CH; c++) {
        const U2* rowu = (const U2*)(base + c * chStride);
        U2 P0 = rowu[0];
        U2 P1 = rowu[1];
        U2 P2 = rowu[2];
        ull m0 = cE0[c], m1 = cE1[c];
        float c0, c1, c2, c3;
        upk(m0, c0, c1); upk(m1, c2, c3);
        ull mM = pk(c1, c2);
        ffma2(aE0[0], m0, P0.lo); ffma2(aE1[0], m1, P0.hi);
        ffma2(aE0[1], m0, P0.hi); ffma2(aE1[1], m1, P1.lo);
        ffma2(aE0[2], m0, P1.lo); ffma2(aE1[2], m1, P1.hi);
        ffma2(aE0[3], m0, P1.hi); ffma2(aE1[3], m1, P2.lo);
        ffma2(aE0[4], m0, P2.lo); ffma2(aE1[4], m1, P2.hi);
        ffma2(aM[0], mM, P0.hi); ffma2(aM[1], mM, P1.lo);
        ffma2(aM[2], mM, P1.hi); ffma2(aM[3], mM, P2.lo);
        float g0, g1, g2, g3, g4, g5, g6, g7, g8, g9, g10, g11;
        upk(P0.lo, g0, g1); upk(P0.hi, g2, g3);
        upk(P1.lo, g4, g5); upk(P1.hi, g6, g7);
        upk(P2.lo, g8, g9); upk(P2.hi, g10, g11);
        a0s[0] = fmaf(c0, g1, a0s[0]);  a3s[0] = fmaf(c3, g4,  a3s[0]);
        a0s[1] = fmaf(c0, g3, a0s[1]);  a3s[1] = fmaf(c3, g6,  a3s[1]);
        a0s[2] = fmaf(c0, g5, a0s[2]);  a3s[2] = fmaf(c3, g8,  a3s[2]);
        a0s[3] = fmaf(c0, g7, a0s[3]);  a3s[3] = fmaf(c3, g10, a3s[3]);
    }

    #pragma unroll
    for (int dj = 0; dj < 9; dj++) {
        float c0, c1, c2, c3;
        if ((dj & 1) == 0) {
            upk(aE0[dj >> 1], c0, c1); upk(aE1[dj >> 1], c2, c3);
        } else {
            c0 = a0s[dj >> 1]; upk(aM[dj >> 1], c1, c2); c3 = a3s[dj >> 1];
        }
        float c4 = __shfl_down_sync(FULL, c0, 1);
        float c5 = __shfl_down_sync(FULL, c1, 1);
        float t12 = c1 + c2, t34 = c3 + c4;
        h[dj][0] = c0 + t12;
        h[dj][1] = t12 + c3;
        h[dj][2] = c2 + t34;
        h[dj][3] = t34 + c5;
    }
}

__global__ __launch_bounds__(NT, 2)
void noisecorr_kernel(const float* __restrict__ noise, float* __restrict__ out)
{
    extern __shared__ float smem[];
    const int t   = threadIdx.x;
    const int bid = blockIdx.x;

    if (bid < N_MAIN) {
        // ====== MAIN: di 4..8 direct + mirrors; double-buffered sHS, 1 bar/iter ===
        float* sN = smem;
        const int b   = bid >> 6;
        const int rem = bid & 63;
        const int ty  = rem >> 3;
        const int tx  = rem & 7;
        const int y0  = ty * 24;
        const int tx0 = tx * 24;
        const float* nb = noise + (size_t)b * CH * H * W;

        for (int idx = t; idx < CH * NH * 10; idx += NT) {
            int c   = idx / (NH * 10);
            int r2  = idx - c * (NH * 10);
            int nr  = r2 / 10;
            int j   = r2 - nr * 10;
            int gy = y0 - 1 + nr;
            int gx = tx0 - 8 + 4 * j;
            float4 v = make_float4(0.f, 0.f, 0.f, 0.f);
            if ((unsigned)gy < (unsigned)H && (unsigned)gx < (unsigned)W)
                v = *(const float4*)&nb[(c * H + gy) * W + gx];
            v.x *= SCL; v.y *= SCL; v.z *= SCL; v.w *= SCL;
            float* dst = &sN[(c * NH + nr) * NW];
            if (j == 0) {
                dst[0] = v.w;
            } else if (j == 9) {
                dst[33] = v.x; dst[34] = v.y; dst[35] = v.z;
            } else {
                int L = 4 * j - 3;
                dst[L] = v.x;
                *(float2*)&dst[L + 1] = make_float2(v.y, v.z);
                dst[L + 3] = v.w;
            }
        }
        __syncthreads();

        const int r  = t >> 3;
        const int g  = t & 7;
        const int q0 = g * 4;
        const int qc = min(q0, 24);
        const int qv = min(q0, 20);
        const int rc = min(r, 25);
        const bool hstore = (r < 26) && (g < 6);
        const bool vstore = (r >= 1) && (r <= 24) && (g <= 5);
        const int  rv = min(max(r, 1), 24);
        const bool xs = (tx >= 1) && (tx <= 6);
        const bool ys = (ty != 7);

        ull cE0[CH], cE1[CH];
        #pragma unroll
        for (int c = 0; c < CH; c++) {
            U2 cv = *(const U2*)&sN[(c * NH + rc) * NW + qc + 4];
            cE0[c] = cv.lo;
            cE1[c] = cv.hi;
        }

        const int oy = y0 + r - 1;
        float* const obase = out + (size_t)b * 81 * HWsz + (size_t)oy * W + tx0 + q0;

        auto run_iter = [&](int k, auto ndjc) {
            constexpr int NDJ = decltype(ndjc)::value;   // 5 (k==0) or 9
            constexpr int NE = (NDJ + 1) / 2;
            constexpr int NO = NDJ / 2;
            ull aE0[NE], aE1[NE], aM[NO];
            float a0s[NO], a3s[NO];
            #pragma unroll
            for (int i = 0; i < NE; i++) { aE0[i] = 0ull; aE1[i] = 0ull; }
            #pragma unroll
            for (int i = 0; i < NO; i++) { aM[i] = 0ull; a0s[i] = 0.f; a3s[i] = 0.f; }

            const float* srow = &sN[(rc + k) * NW + qc];
            #pragma unroll
            for (int c = 0; c < CH; c++) {
                const U2* rowu = (const U2*)srow;
                U2 P0 = rowu[0];
                ull E[6];
                E[0] = P0.lo; E[1] = P0.hi;
                ull m0 = cE0[c], m1 = cE1[c];
                float c0, c1, c2, c3;
                upk(m0, c0, c1); upk(m1, c2, c3);
                float g4, g5, g6, g7;
                U2 P2;
                if constexpr (NDJ == 9) {
                    U2 P1 = rowu[1];
                    P2 = rowu[2];
                    E[2] = P1.lo; E[3] = P1.hi;
                    E[4] = P2.lo; E[5] = P2.hi;
                    upk(P1.lo, g4, g5); upk(P1.hi, g6, g7);
                } else {
                    // k==0: shifted row IS the center row -> middle float4 already in regs
                    E[2] = m0; E[3] = m1;
                    g4 = c0; g5 = c1; g6 = c2; g7 = c3;
                }
                srow += NH * NW;
                ull mM = pk(c1, c2);
                #pragma unroll
                for (int e = 0; e < NE; e++) {
                    ffma2(aE0[e], m0, E[e]); ffma2(aE1[e], m1, E[e + 1]);
                }
                #pragma unroll
                for (int o = 0; o < NO; o++) ffma2(aM[o], mM, E[o + 1]);
                float g0, g1, g2, g3;
                upk(P0.lo, g0, g1); upk(P0.hi, g2, g3);
                a0s[0] = fmaf(c0, g1, a0s[0]);  a3s[0] = fmaf(c3, g4, a3s[0]);
                a0s[1] = fmaf(c0, g3, a0s[1]);  a3s[1] = fmaf(c3, g6, a3s[1]);
                if constexpr (NDJ == 9) {
                    float g8, g9, g10, g11;
                    upk(P2.lo, g8, g9); upk(P2.hi, g10, g11);
                    a0s[2] = fmaf(c0, g5, a0s[2]);  a3s[2] = fmaf(c3, g8,  a3s[2]);
                    a0s[3] = fmaf(c0, g7, a0s[3]);  a3s[3] = fmaf(c3, g10, a3s[3]);
                }
            }

            float h[NDJ][4];
            #pragma unroll
            for (int dj = 0; dj < NDJ; dj++) {
                float c0, c1, c2, c3;
                if ((dj & 1) == 0) {
                    upk(aE0[dj >> 1], c0, c1); upk(aE1[dj >> 1], c2, c3);
                } else {
                    c0 = a0s[dj >> 1]; upk(aM[dj >> 1], c1, c2); c3 = a3s[dj >> 1];
                }
                float c4 = __shfl_down_sync(FULL, c0, 1);
                float c5 = __shfl_down_sync(FULL, c1, 1);
                float t12 = c1 + c2, t34 = c3 + c4;
                h[dj][0] = c0 + t12;
                h[dj][1] = t12 + c3;
                h[dj][2] = c2 + t34;
                h[dj][3] = t34 + c5;
            }

            float* sHS = smem + SN_FLOATS + (k & 1) * SHS_FLOATS;
            if (hstore) {
                #pragma unroll
                for (int dj = 0; dj < NDJ; dj++)
                    *(float4*)&sHS[(dj * CRH + r) * HSR + q0] =
                        make_float4(h[dj][0], h[dj][1], h[dj][2], h[dj][3]);
            }
            __syncthreads();

            float* const obk = obase + (size_t)(k + 4) * 9 * HWsz;
            float* const omk9 = obase + 80 * HWsz - (size_t)(k + 4) * 9 * HWsz
                                + (ptrdiff_t)k * W - 4;
            float* const omk0 = obase + 44 * HWsz - 4;

            #pragma unroll
            for (int dj = 0; dj < NDJ; dj++) {
                U2 hmU = *(const U2*)&sHS[(dj * CRH + rv - 1) * HSR + qv];
                U2 hpU = *(const U2*)&sHS[(dj * CRH + rv + 1) * HSR + qv];
                if (vstore) {
                    ull s0 = add2(hmU.lo, hpU.lo);
                    ull s1 = add2(hmU.hi, hpU.hi);
                    float s0x, s0y, s1x, s1y;
                    upk(s0, s0x, s0y); upk(s1, s1x, s1y);
                    float4 o4;
                    o4.x = s0x + h[dj][0];
                    o4.y = s0y + h[dj][1];
                    o4.z = s1x + h[dj][2];
                    o4.w = s1y + h[dj][3];
                    float* ob = obk + (ptrdiff_t)dj * (ptrdiff_t)HWsz;
                    *(float4*)ob = o4;

                    if constexpr (NDJ == 9) {
                        // k>=1 mirror: out_{80-p}(y+k, x+dj-4); y in [4,191], x in [4,187]
                        const int ym = oy + k;
                        if (ys || ym < H) {
                            const int xb = tx0 + q0 + (dj - 4);
                            float* om = omk9 + (ptrdiff_t)dj * (1 - (ptrdiff_t)HWsz);
                            if (xs) {
                                if (dj == 4) {
                                    *(float4*)&om[0] = o4;           // aligned STG.128
                                } else if ((dj & 1) == 0) {
                                    *(float2*)&om[0] = make_float2(o4.x, o4.y);
                                    *(float2*)&om[2] = make_float2(o4.z, o4.w);
                                } else {
                                    om[0] = o4.x;
                                    *(float2*)&om[1] = make_float2(o4.y, o4.z);
                                    om[3] = o4.w;
                                }
                            } else {
                                if ((unsigned)(xb + 0 - 4) < 184u) om[0] = o4.x;
                                if ((unsigned)(xb + 1 - 4) < 184u) om[1] = o4.y;
                                if ((unsigned)(xb + 2 - 4) < 184u) om[2] = o4.z;
                                if ((unsigned)(xb + 3 - 4) < 184u) om[3] = o4.w;
                            }
                        }
                    } else {
                        // k==0 mirror (dj<4): out_{44-dj}(y, x+dj-4); x in [0,187]
                        if (dj < 4) {
                            const int xb = tx0 + q0 + (dj - 4);
                            float* om = omk0 + (ptrdiff_t)dj * (1 - (ptrdiff_t)HWsz);
                            if (xs) {
                                if ((dj & 1) == 0) {
                                    *(float2*)&om[0] = make_float2(o4.x, o4.y);
                                    *(float2*)&om[2] = make_float2(o4.z, o4.w);
                                } else {
                                    om[0] = o4.x;
                                    *(float2*)&om[1] = make_float2(o4.y, o4.z);
                                    om[3] = o4.w;
                                }
                            } else {
                                if ((unsigned)(xb + 0) < 188u) om[0] = o4.x;
                                if ((unsigned)(xb + 1) < 188u) om[1] = o4.y;
                                if ((unsigned)(xb + 2) < 188u) om[2] = o4.z;
                                if ((unsigned)(xb + 3) < 188u) om[3] = o4.w;
                            }
                        }
                    }
                }
            }
        };

        run_iter(0, Ic<5>{});
        #pragma unroll 1
        for (int k = 1; k < 5; k++)
            run_iter(k, Ic<9>{});

    } else if (bid < N_MAIN + N_TOP) {
        // ===== TOP STRIP: planes di 0..3 (rows 0..3, full width) + di=4 right corner
        float* sN  = smem;
        float* sHS = smem + T_SN;
        const int idx0 = bid - N_MAIN;
        const int b    = idx0 >> 1;
        const int tx0  = (idx0 & 1) * 96;
        const float* nb = noise + (size_t)b * CH * H * W;

        for (int idx = t; idx < T_SN; idx += NT) {
            int c   = idx / (T_NH * T_NW);
            int r2  = idx - c * (T_NH * T_NW);
            int nr  = r2 / T_NW;
            int nc  = r2 - nr * T_NW;
            int gy = nr - 5, gx = tx0 - 5 + nc;
            float v = 0.0f;
            if ((unsigned)gy < (unsigned)H && (unsigned)gx < (unsigned)W)
                v = nb[(c * H + gy) * W + gx] * SCL;
            sN[idx] = v;
        }
        __syncthreads();

        const int r  = t >> 5;
        const int g  = t & 31;
        const int q0 = g * 4;
        const int qc = min(q0, 96);
        const int qv = min(q0, 92);
        const int rc = min(r, 5);
        const bool hstore = (r < 6) && (g < 24);
        const bool vstore = (r >= 1) && (r <= 4) && (g <= 23);
        const int  rv = min(max(r, 1), 4);
        const bool corner = (tx0 == 96) && (q0 == 92);

        ull cE0[CH], cE1[CH];
        #pragma unroll
        for (int c = 0; c < CH; c++) {
            U2 cv = *(const U2*)&sN[(c * T_NH + rc + 4) * T_NW + qc + 4];
            cE0[c] = cv.lo;
            cE1[c] = cv.hi;
        }

        #pragma unroll 1
        for (int di = 0; di < 5; di++) {
            float h[9][4];
            corr_hsum(&sN[(rc + di) * T_NW + qc], T_NH * T_NW, cE0, cE1, h);

            __syncthreads();
            if (hstore) {
                #pragma unroll
                for (int dj = 0; dj < 9; dj++)
                    *(float4*)&sHS[(dj * T_CR + r) * T_HSR + q0] =
                        make_float4(h[dj][0], h[dj][1], h[dj][2], h[dj][3]);
            }
            __syncthreads();

            const int oy = r - 1;
            #pragma unroll
            for (int dj = 0; dj < 9; dj++) {
                float4 hm = *(const float4*)&sHS[(dj * T_CR + rv - 1) * T_HSR + qv];
                float4 hp = *(const float4*)&sHS[(dj * T_CR + rv + 1) * T_HSR + qv];
                bool st = vstore && (di < 4 || (corner && dj >= 5));
                if (st) {
                    float4 o;
                    o.x = hm.x + h[dj][0] + hp.x;
                    o.y = hm.y + h[dj][1] + hp.y;
                    o.z = hm.z + h[dj][2] + hp.z;
                    o.w = hm.w + h[dj][3] + hp.w;
                    const int p = di * 9 + dj;
                    float* ob = out + (((size_t)b * 81 + p) * H + oy) * W + tx0 + q0;
                    *(float4*)ob = o;
                }
            }
        }
    } else {
        // ===== SIDE STRIPS: planes di 0..3 (cols 0..3 & 188..191) + di=4 right dj>=5
        float* sNL  = smem;
        float* sNR  = smem + S_SN;
        float* sHSL = smem + 2 * S_SN;
        float* sHSR = smem + 2 * S_SN + S_HS;
        const int idx0 = bid - N_MAIN - N_TOP;
        const int b = idx0 >> 3;
        const int k = idx0 & 7;
        const int y0 = (k == 7) ? 168 : 4 + 24 * k;
        const float* nb = noise + (size_t)b * CH * H * W;

        for (int idx = t; idx < 2 * S_SN; idx += NT) {
            int side = idx / S_SN;
            int w2   = idx - side * S_SN;
            int c    = w2 / (S_NH * S_NW);
            int r2   = w2 - c * (S_NH * S_NW);
            int nr   = r2 >> 4;
            int nc   = r2 & 15;
            int gy = y0 - 5 + nr;
            int gx = (side ? 183 : -5) + nc;
            float v = 0.0f;
            if ((unsigned)gy < (unsigned)H && (unsigned)gx < (unsigned)W)
                v = nb[(c * H + gy) * W + gx] * SCL;
            smem[side ? (S_SN + w2) : w2] = v;
        }
        __syncthreads();

        const bool active = (t < 128);
        const int r  = t >> 2;
        const int g  = t & 3;
        const int gg = g & 1;
        const int sd = g >> 1;
        const int q0 = gg * 4;
        const int rc = min(r, 25);
        const bool hstore = active && (gg == 0) && (r < 26);
        const bool vstore = active && (gg == 0) && (r >= 1) && (r <= 24);
        const int  rv = min(max(r, 1), 24);
        float* sNs  = sd ? sNR : sNL;
        float* sHSs = sd ? sHSR : sHSL;
        const int ox = sd ? 188 : 0;

        ull cE0[CH], cE1[CH];
        if (active) {
            #pragma unroll
            for (int c = 0; c < CH; c++) {
                U2 cv = *(const U2*)&sNs[(c * S_NH + rc + 4) * S_NW + q0 + 4];
                cE0[c] = cv.lo;
                cE1[c] = cv.hi;
            }
        }

        #pragma unroll 1
        for (int di = 0; di < 5; di++) {
            float h[9][4];
            if (active)
                corr_hsum(&sNs[(rc + di) * S_NW + q0], S_NH * S_NW, cE0, cE1, h);

            __syncthreads();
            if (hstore) {
                #pragma unroll
                for (int dj = 0; dj < 9; dj++)
                    *(float4*)&sHSs[(dj * S_CR + r) * S_HSR] =
                        make_float4(h[dj][0], h[dj][1], h[dj][2], h[dj][3]);
            }
            __syncthreads();

            if (active) {
                const int oy = y0 + r - 1;
                #pragma unroll
                for (int dj = 0; dj < 9; dj++) {
                    float4 hm = *(const float4*)&sHSs[(dj * S_CR + rv - 1) * S_HSR];
                    float4 hp = *(const float4*)&sHSs[(dj * S_CR + rv + 1) * S_HSR];
                    bool st = vstore && (di < 4 || (sd == 1 && dj >= 5));
                    if (st) {
                        float4 o;
                        o.x = hm.x + h[dj][0] + hp.x;
                        o.y = hm.y + h[dj][1] + hp.y;
                        o.z = hm.z + h[dj][2] + hp.z;
                        o.w = hm.w + h[dj][3] + hp.w;
                        const int p = di * 9 + dj;
                        float* ob = out + (((size_t)b * 81 + p) * H + oy) * W + ox;
                        *(float4*)ob = o;
                    }
                }
            }
        }
    }
}

extern "C" void kernel_launch(void* const* d_in, const int* in_sizes, int n_in,
                              void* d_out, int out_size)
{
    const float* noise = (const float*)d_in[0];
    float* out = (float*)d_out;
    (void)in_sizes; (void)n_in; (void)out_size;

    cudaFuncSetAttribute(noisecorr_kernel,
                         cudaFuncAttributeMaxDynamicSharedMemorySize, SMEM_BYTES);

    noisecorr_kernel<<<NBLOCKS, NT, SMEM_BYTES>>>(noise, out);
}

// round 16
// speedup vs baseline: 1.2707x; 1.0296x over previous
#include <cuda_runtime.h>

using ull = unsigned long long;

namespace {
constexpr int CH = 16;
constexpr int H = 192, W = 192;
constexpr size_t HWsz = (size_t)H * W;
constexpr unsigned FULL = 0xffffffffu;
constexpr int NT = 256;
constexpr float SCL = 1.0f / 12.0f;   // both operands scaled -> product carries 1/144

constexpr int NH = 30, NW = 36;
constexpr int CRH = 26;
constexpr int HSR = 24;
constexpr int SN_FLOATS  = CH * NH * NW;     // 17280
constexpr int SHS_FLOATS = 9 * CRH * HSR;    // 5616
constexpr int SMEM_BYTES = (SN_FLOATS + 2 * SHS_FLOATS) * 4;  // 114048

constexpr int T_NH = 10, T_NW = 108, T_HSR = 96, T_CR = 6;
constexpr int T_SN = CH * T_NH * T_NW;
constexpr int S_NH = 30, S_NW = 16, S_HSR = 4, S_CR = 26;
constexpr int S_SN = CH * S_NH * S_NW;
constexpr int S_HS = 9 * S_CR * S_HSR;

constexpr int N_MAIN = 512;
constexpr int N_TOP  = 16;
constexpr int N_SIDE = 64;
constexpr int NBLOCKS = N_MAIN + N_TOP + N_SIDE;  // 592
}

template<int N> struct Ic { static constexpr int value = N; };

struct alignas(16) U2 { ull lo, hi; };

__device__ __forceinline__ ull pk(float lo, float hi) {
    ull r; asm("mov.b64 %0, {%1,%2};" : "=l"(r) : "f"(lo), "f"(hi)); return r;
}
__device__ __forceinline__ void upk(ull v, float& lo, float& hi) {
    asm("mov.b64 {%0,%1}, %2;" : "=f"(lo), "=f"(hi) : "l"(v));
}
__device__ __forceinline__ void ffma2(ull& acc, ull m, ull s) {
    asm("fma.rn.f32x2 %0, %1, %2, %0;" : "+l"(acc) : "l"(m), "l"(s));
}
__device__ __forceinline__ ull add2(ull a, ull b) {
    ull r; asm("add.rn.f32x2 %0, %1, %2;" : "=l"(r) : "l"(a), "l"(b)); return r;
}

// strip helper: corr (16ch, 4 cols, 9 dj) + horizontal 3-sum. sN pre-scaled.
__device__ __forceinline__ void corr_hsum(const float* __restrict__ base, int chStride,
                                          const ull* __restrict__ cE0,
                                          const ull* __restrict__ cE1,
                                          float (&h)[9][4])
{
    ull aE0[5], aE1[5], aM[4];
    float a0s[4], a3s[4];
    #pragma unroll
    for (int i = 0; i < 5; i++) { aE0[i] = 0ull; aE1[i] = 0ull; }
    #pragma unroll
    for (int i = 0; i < 4; i++) { aM[i] = 0ull; a0s[i] = 0.0f; a3s[i] = 0.0f; }

    #pragma unroll
    for (int c = 0; c < CH; c++) {
        const U2* rowu = (const U2*)(base + c * chStride);
        U2 P0 = rowu[0];
        U2 P1 = rowu[1];
        U2 P2 = rowu[2];
        ull m0 = cE0[c], m1 = cE1[c];
        float c0, c1, c2, c3;
        upk(m0, c0, c1); upk(m1, c2, c3);
        ull mM = pk(c1, c2);
        ffma2(aE0[0], m0, P0.lo); ffma2(aE1[0], m1, P0.hi);
        ffma2(aE0[1], m0, P0.hi); ffma2(aE1[1], m1, P1.lo);
        ffma2(aE0[2], m0, P1.lo); ffma2(aE1[2], m1, P1.hi);
        ffma2(aE0[3], m0, P1.hi); ffma2(aE1[3], m1, P2.lo);
        ffma2(aE0[4], m0, P2.lo); ffma2(aE1[4], m1, P2.hi);
        ffma2(aM[0], mM, P0.hi); ffma2(aM[1], mM, P1.lo);
        ffma2(aM[2], mM, P1.hi); ffma2(aM[3], mM, P2.lo);
        float g0, g1, g2, g3, g4, g5, g6, g7, g8, g9, g10, g11;
        upk(P0.lo, g0, g1); upk(P0.hi, g2, g3);
        upk(P1.lo, g4, g5); upk(P1.hi, g6, g7);
        upk(P2.lo, g8, g9); upk(P2.hi, g10, g11);
        a0s[0] = fmaf(c0, g1, a0s[0]);  a3s[0] = fmaf(c3, g4,  a3s[0]);
        a0s[1] = fmaf(c0, g3, a0s[1]);  a3s[1] = fmaf(c3, g6,  a3s[1]);
        a0s[2] = fmaf(c0, g5, a0s[2]);  a3s[2] = fmaf(c3, g8,  a3s[2]);
        a0s[3] = fmaf(c0, g7, a0s[3]);  a3s[3] = fmaf(c3, g10, a3s[3]);
    }

    #pragma unroll
    for (int dj = 0; dj < 9; dj++) {
        float c0, c1, c2, c3;
        if ((dj & 1) == 0) {
            upk(aE0[dj >> 1], c0, c1); upk(aE1[dj >> 1], c2, c3);
        } else {
            c0 = a0s[dj >> 1]; upk(aM[dj >> 1], c1, c2); c3 = a3s[dj >> 1];
        }
        float c4 = __shfl_down_sync(FULL, c0, 1);
        float c5 = __shfl_down_sync(FULL, c1, 1);
        float t12 = c1 + c2, t34 = c3 + c4;
        h[dj][0] = c0 + t12;
        h[dj][1] = t12 + c3;
        h[dj][2] = c2 + t34;
        h[dj][3] = t34 + c5;
    }
}

__global__ __launch_bounds__(NT, 2)
void noisecorr_kernel(const float* __restrict__ noise, float* __restrict__ out)
{
    extern __shared__ float smem[];
    const int t   = threadIdx.x;
    const int bid = blockIdx.x;

    if (bid < N_MAIN) {
        // ====== MAIN: di 4..8 direct + mirrors; double-buffered sHS, 1 bar/iter ===
        float* sN = smem;
        const int b   = bid >> 6;
        const int rem = bid & 63;
        const int ty  = rem >> 3;
        const int tx  = rem & 7;
        const int y0  = ty * 24;
        const int tx0 = tx * 24;
        const float* nb = noise + (size_t)b * CH * H * W;

        for (int idx = t; idx < CH * NH * 10; idx += NT) {
            int c   = idx / (NH * 10);
            int r2  = idx - c * (NH * 10);
            int nr  = r2 / 10;
            int j   = r2 - nr * 10;
            int gy = y0 - 1 + nr;
            int gx = tx0 - 8 + 4 * j;
            float4 v = make_float4(0.f, 0.f, 0.f, 0.f);
            if ((unsigned)gy < (unsigned)H && (unsigned)gx < (unsigned)W)
                v = *(const float4*)&nb[(c * H + gy) * W + gx];
            v.x *= SCL; v.y *= SCL; v.z *= SCL; v.w *= SCL;
            float* dst = &sN[(c * NH + nr) * NW];
            if (j == 0) {
                dst[0] = v.w;
            } else if (j == 9) {
                dst[33] = v.x; dst[34] = v.y; dst[35] = v.z;
            } else {
                int L = 4 * j - 3;
                dst[L] = v.x;
                *(float2*)&dst[L + 1] = make_float2(v.y, v.z);
                dst[L + 3] = v.w;
            }
        }
        __syncthreads();

        const int r  = t >> 3;
        const int g  = t & 7;
        const int q0 = g * 4;
        const int qc = min(q0, 24);
        const int qv = min(q0, 20);
        const int rc = min(r, 25);
        const bool work = (t < 224);   // warp 7 (r=28..31) produces nothing: skip its LSU/FMA stream
        const bool hstore = (r < 26) && (g < 6);
        const bool vstore = (r >= 1) && (r <= 24) && (g <= 5);
        const int  rv = min(max(r, 1), 24);
        const bool xs = (tx >= 1) && (tx <= 6);
        const bool ys = (ty != 7);

        ull cE0[CH], cE1[CH];
        #pragma unroll
        for (int c = 0; c < CH; c++) {
            U2 cv = *(const U2*)&sN[(c * NH + rc) * NW + qc + 4];
            cE0[c] = cv.lo;
            cE1[c] = cv.hi;
        }

        const int oy = y0 + r - 1;
        float* const obase = out + (size_t)b * 81 * HWsz + (size_t)oy * W + tx0 + q0;

        auto run_iter = [&](int k, auto ndjc) {
            constexpr int NDJ = decltype(ndjc)::value;   // 5 (k==0) or 9
            constexpr int NE = (NDJ + 1) / 2;
            constexpr int NO = NDJ / 2;

            float h[NDJ][4];
            if (work) {
                ull aE0[NE], aE1[NE], aM[NO];
                float a0s[NO], a3s[NO];
                #pragma unroll
                for (int i = 0; i < NE; i++) { aE0[i] = 0ull; aE1[i] = 0ull; }
                #pragma unroll
                for (int i = 0; i < NO; i++) { aM[i] = 0ull; a0s[i] = 0.f; a3s[i] = 0.f; }

                const float* srow = &sN[(rc + k) * NW + qc];
                #pragma unroll
                for (int c = 0; c < CH; c++) {
                    const U2* rowu = (const U2*)srow;
                    U2 P0 = rowu[0];
                    ull E[6];
                    E[0] = P0.lo; E[1] = P0.hi;
                    ull m0 = cE0[c], m1 = cE1[c];
                    float c0, c1, c2, c3;
                    upk(m0, c0, c1); upk(m1, c2, c3);
                    float g4, g5, g6, g7;
                    U2 P2;
                    if constexpr (NDJ == 9) {
                        U2 P1 = rowu[1];
                        P2 = rowu[2];
                        E[2] = P1.lo; E[3] = P1.hi;
                        E[4] = P2.lo; E[5] = P2.hi;
                        upk(P1.lo, g4, g5); upk(P1.hi, g6, g7);
                    } else {
                        // k==0: shifted row IS the center row
                        E[2] = m0; E[3] = m1;
                        g4 = c0; g5 = c1; g6 = c2; g7 = c3;
                    }
                    srow += NH * NW;
                    ull mM = pk(c1, c2);
                    #pragma unroll
                    for (int e = 0; e < NE; e++) {
                        ffma2(aE0[e], m0, E[e]); ffma2(aE1[e], m1, E[e + 1]);
                    }
                    #pragma unroll
                    for (int o = 0; o < NO; o++) ffma2(aM[o], mM, E[o + 1]);
                    float g0, g1, g2, g3;
                    upk(P0.lo, g0, g1); upk(P0.hi, g2, g3);
                    a0s[0] = fmaf(c0, g1, a0s[0]);  a3s[0] = fmaf(c3, g4, a3s[0]);
                    a0s[1] = fmaf(c0, g3, a0s[1]);  a3s[1] = fmaf(c3, g6, a3s[1]);
                    if constexpr (NDJ == 9) {
                        float g8, g9, g10, g11;
                        upk(P2.lo, g8, g9); upk(P2.hi, g10, g11);
                        a0s[2] = fmaf(c0, g5, a0s[2]);  a3s[2] = fmaf(c3, g8,  a3s[2]);
                        a0s[3] = fmaf(c0, g7, a0s[3]);  a3s[3] = fmaf(c3, g10, a3s[3]);
                    }
                }

                #pragma unroll
                for (int dj = 0; dj < NDJ; dj++) {
                    float c0, c1, c2, c3;
                    if ((dj & 1) == 0) {
                        upk(aE0[dj >> 1], c0, c1); upk(aE1[dj >> 1], c2, c3);
                    } else {
                        c0 = a0s[dj >> 1]; upk(aM[dj >> 1], c1, c2); c3 = a3s[dj >> 1];
                    }
                    float c4 = __shfl_down_sync(FULL, c0, 1);
                    float c5 = __shfl_down_sync(FULL, c1, 1);
                    float t12 = c1 + c2, t34 = c3 + c4;
                    h[dj][0] = c0 + t12;
                    h[dj][1] = t12 + c3;
                    h[dj][2] = c2 + t34;
                    h[dj][3] = t34 + c5;
                }
            }

            float* sHS = smem + SN_FLOATS + (k & 1) * SHS_FLOATS;
            if (hstore) {
                #pragma unroll
                for (int dj = 0; dj < NDJ; dj++)
                    *(float4*)&sHS[(dj * CRH + r) * HSR + q0] =
                        make_float4(h[dj][0], h[dj][1], h[dj][2], h[dj][3]);
            }
            __syncthreads();

            if (work) {
                float* const obk = obase + (size_t)(k + 4) * 9 * HWsz;
                float* const omk9 = obase + 80 * HWsz - (size_t)(k + 4) * 9 * HWsz
                                    + (ptrdiff_t)k * W - 4;
                float* const omk0 = obase + 44 * HWsz - 4;

                #pragma unroll
                for (int dj = 0; dj < NDJ; dj++) {
                    U2 hmU = *(const U2*)&sHS[(dj * CRH + rv - 1) * HSR + qv];
                    U2 hpU = *(const U2*)&sHS[(dj * CRH + rv + 1) * HSR + qv];
                    if (vstore) {
                        ull s0 = add2(hmU.lo, hpU.lo);
                        ull s1 = add2(hmU.hi, hpU.hi);
                        float s0x, s0y, s1x, s1y;
                        upk(s0, s0x, s0y); upk(s1, s1x, s1y);
                        float4 o4;
                        o4.x = s0x + h[dj][0];
                        o4.y = s0y + h[dj][1];
                        o4.z = s1x + h[dj][2];
                        o4.w = s1y + h[dj][3];
                        float* ob = obk + (ptrdiff_t)dj * (ptrdiff_t)HWsz;
                        *(float4*)ob = o4;

                        if constexpr (NDJ == 9) {
                            // k>=1 mirror: out_{80-p}(y+k, x+dj-4); y in [4,191], x in [4,187]
                            const int ym = oy + k;
                            if (ys || ym < H) {
                                const int xb = tx0 + q0 + (dj - 4);
                                float* om = omk9 + (ptrdiff_t)dj * (1 - (ptrdiff_t)HWsz);
                                if (xs) {
                                    if (dj == 0 || dj == 4 || dj == 8) {
                                        *(float4*)&om[0] = o4;       // s = -4,0,+4: aligned
                                    } else if ((dj & 1) == 0) {
                                        *(float2*)&om[0] = make_float2(o4.x, o4.y);
                                        *(float2*)&om[2] = make_float2(o4.z, o4.w);
                                    } else {
                                        om[0] = o4.x;
                                        *(float2*)&om[1] = make_float2(o4.y, o4.z);
                                        om[3] = o4.w;
                                    }
                                } else {
                                    if ((unsigned)(xb + 0 - 4) < 184u) om[0] = o4.x;
                                    if ((unsigned)(xb + 1 - 4) < 184u) om[1] = o4.y;
                                    if ((unsigned)(xb + 2 - 4) < 184u) om[2] = o4.z;
                                    if ((unsigned)(xb + 3 - 4) < 184u) om[3] = o4.w;
                                }
                            }
                        } else {
                            // k==0 mirror (dj<4): out_{44-dj}(y, x+dj-4); x in [0,187]
                            if (dj < 4) {
                                const int xb = tx0 + q0 + (dj - 4);
                                float* om = omk0 + (ptrdiff_t)dj * (1 - (ptrdiff_t)HWsz);
                                if (xs) {
                                    if (dj == 0) {
                                        *(float4*)&om[0] = o4;       // s = -4: aligned
                                    } else if ((dj & 1) == 0) {
                                        *(float2*)&om[0] = make_float2(o4.x, o4.y);
                                        *(float2*)&om[2] = make_float2(o4.z, o4.w);
                                    } else {
                                        om[0] = o4.x;
                                        *(float2*)&om[1] = make_float2(o4.y, o4.z);
                                        om[3] = o4.w;
                                    }
                                } else {
                                    if ((unsigned)(xb + 0) < 188u) om[0] = o4.x;
                                    if ((unsigned)(xb + 1) < 188u) om[1] = o4.y;
                                    if ((unsigned)(xb + 2) < 188u) om[2] = o4.z;
                                    if ((unsigned)(xb + 3) < 188u) om[3] = o4.w;
                                }
                            }
                        }
                    }
                }
            }
        };

        run_iter(0, Ic<5>{});
        #pragma unroll 1
        for (int k = 1; k < 5; k++)
            run_iter(k, Ic<9>{});

    } else if (bid < N_MAIN + N_TOP) {
        // ===== TOP STRIP: planes di 0..3 (rows 0..3, full width) + di=4 right corner
        float* sN  = smem;
        float* sHS = smem + T_SN;
        const int idx0 = bid - N_MAIN;
        const int b    = idx0 >> 1;
        const int tx0  = (idx0 & 1) * 96;
        const float* nb = noise + (size_t)b * CH * H * W;

        for (int idx = t; idx < T_SN; idx += NT) {
            int c   = idx / (T_NH * T_NW);
            int r2  = idx - c * (T_NH * T_NW);
            int nr  = r2 / T_NW;
            int nc  = r2 - nr * T_NW;
            int gy = nr - 5, gx = tx0 - 5 + nc;
            float v = 0.0f;
            if ((unsigned)gy < (unsigned)H && (unsigned)gx < (unsigned)W)
                v = nb[(c * H + gy) * W + gx] * SCL;
            sN[idx] = v;
        }
        __syncthreads();

        const int r  = t >> 5;
        const int g  = t & 31;
        const int q0 = g * 4;
        const int qc = min(q0, 96);
        const int qv = min(q0, 92);
        const int rc = min(r, 5);
        const bool work = (t < 192);   // warps 6,7 (rows 6,7) produce nothing
        const bool hstore = (r < 6) && (g < 24);
        const bool vstore = (r >= 1) && (r <= 4) && (g <= 23);
        const int  rv = min(max(r, 1), 4);
        const bool corner = (tx0 == 96) && (q0 == 92);

        ull cE0[CH], cE1[CH];
        #pragma unroll
        for (int c = 0; c < CH; c++) {
            U2 cv = *(const U2*)&sN[(c * T_NH + rc + 4) * T_NW + qc + 4];
            cE0[c] = cv.lo;
            cE1[c] = cv.hi;
        }

        #pragma unroll 1
        for (int di = 0; di < 5; di++) {
            float h[9][4];
            if (work)
                corr_hsum(&sN[(rc + di) * T_NW + qc], T_NH * T_NW, cE0, cE1, h);

            __syncthreads();
            if (hstore) {
                #pragma unroll
                for (int dj = 0; dj < 9; dj++)
                    *(float4*)&sHS[(dj * T_CR + r) * T_HSR + q0] =
                        make_float4(h[dj][0], h[dj][1], h[dj][2], h[dj][3]);
            }
            __syncthreads();

            if (work) {
                const int oy = r - 1;
                #pragma unroll
                for (int dj = 0; dj < 9; dj++) {
                    float4 hm = *(const float4*)&sHS[(dj * T_CR + rv - 1) * T_HSR + qv];
                    float4 hp = *(const float4*)&sHS[(dj * T_CR + rv + 1) * T_HSR + qv];
                    bool st = vstore && (di < 4 || (corner && dj >= 5));
                    if (st) {
                        float4 o;
                        o.x = hm.x + h[dj][0] + hp.x;
                        o.y = hm.y + h[dj][1] + hp.y;
                        o.z = hm.z + h[dj][2] + hp.z;
                        o.w = hm.w + h[dj][3] + hp.w;
                        const int p = di * 9 + dj;
                        float* ob = out + (((size_t)b * 81 + p) * H + oy) * W + tx0 + q0;
                        *(float4*)ob = o;
                    }
                }
            }
        }
    } else {
        // ===== SIDE STRIPS: planes di 0..3 (cols 0..3 & 188..191) + di=4 right dj>=5
        float* sNL  = smem;
        float* sNR  = smem + S_SN;
        float* sHSL = smem + 2 * S_SN;
        float* sHSR = smem + 2 * S_SN + S_HS;
        const int idx0 = bid - N_MAIN - N_TOP;
        const int b = idx0 >> 3;
        const int k = idx0 & 7;
        const int y0 = (k == 7) ? 168 : 4 + 24 * k;
        const float* nb = noise + (size_t)b * CH * H * W;

        for (int idx = t; idx < 2 * S_SN; idx += NT) {
            int side = idx / S_SN;
            int w2   = idx - side * S_SN;
            int c    = w2 / (S_NH * S_NW);
            int r2   = w2 - c * (S_NH * S_NW);
            int nr   = r2 >> 4;
            int nc   = r2 & 15;
            int gy = y0 - 5 + nr;
            int gx = (side ? 183 : -5) + nc;
            float v = 0.0f;
            if ((unsigned)gy < (unsigned)H && (unsigned)gx < (unsigned)W)
                v = nb[(c * H + gy) * W + gx] * SCL;
            smem[side ? (S_SN + w2) : w2] = v;
        }
        __syncthreads();

        const bool active = (t < 128);
        const int r  = t >> 2;
        const int g  = t & 3;
        const int gg = g & 1;
        const int sd = g >> 1;
        const int q0 = gg * 4;
        const int rc = min(r, 25);
        const bool hstore = active && (gg == 0) && (r < 26);
        const bool vstore = active && (gg == 0) && (r >= 1) && (r <= 24);
        const int  rv = min(max(r, 1), 24);
        float* sNs  = sd ? sNR : sNL;
        float* sHSs = sd ? sHSR : sHSL;
        const int ox = sd ? 188 : 0;

        ull cE0[CH], cE1[CH];
        if (active) {
            #pragma unroll
            for (int c = 0; c < CH; c++) {
                U2 cv = *(const U2*)&sNs[(c * S_NH + rc + 4) * S_NW + q0 + 4];
                cE0[c] = cv.lo;
                cE1[c] = cv.hi;
            }
        }

        #pragma unroll 1
        for (int di = 0; di < 5; di++) {
            float h[9][4];
            if (active)
                corr_hsum(&sNs[(rc + di) * S_NW + q0], S_NH * S_NW, cE0, cE1, h);

            __syncthreads();
            if (hstore) {
                #pragma unroll
                for (int dj = 0; dj < 9; dj++)
                    *(float4*)&sHSs[(dj * S_CR + r) * S_HSR] =
                        make_float4(h[dj][0], h[dj][1], h[dj][2], h[dj][3]);
            }
            __syncthreads();

            if (active) {
                const int oy = y0 + r - 1;
                #pragma unroll
                for (int dj = 0; dj < 9; dj++) {
                    float4 hm = *(const float4*)&sHSs[(dj * S_CR + rv - 1) * S_HSR];
                    float4 hp = *(const float4*)&sHSs[(dj * S_CR + rv + 1) * S_HSR];
                    bool st = vstore && (di < 4 || (sd == 1 && dj >= 5));
                    if (st) {
                        float4 o;
                        o.x = hm.x + h[dj][0] + hp.x;
                        o.y = hm.y + h[dj][1] + hp.y;
                        o.z = hm.z + h[dj][2] + hp.z;
                        o.w = hm.w + h[dj][3] + hp.w;
                        const int p = di * 9 + dj;
                        float* ob = out + (((size_t)b * 81 + p) * H + oy) * W + ox;
                        *(float4*)ob = o;
                    }
                }
            }
        }
    }
}

extern "C" void kernel_launch(void* const* d_in, const int* in_sizes, int n_in,
                              void* d_out, int out_size)
{
    const float* noise = (const float*)d_in[0];
    float* out = (float*)d_out;
    (void)in_sizes; (void)n_in; (void)out_size;

    cudaFuncSetAttribute(noisecorr_kernel,
                         cudaFuncAttributeMaxDynamicSharedMemorySize, SMEM_BYTES);

    noisecorr_kernel<<<NBLOCKS, NT, SMEM_BYTES>>>(noise, out);
}